// round 6
// baseline (speedup 1.0000x reference)
#include <cuda_runtime.h>
#include <math.h>

#define SEQ 2048
#define DIM 2048
#define NH 32
#define NKVH 8
#define HD 64
#define QSTRIDE (NH*HD)     // 2048
#define KSTRIDE (NKVH*HD)   // 512

typedef unsigned long long ull;

// scratch (device globals: no allocation allowed)
__device__ float g_q[SEQ * QSTRIDE];
__device__ float g_k[SEQ * KSTRIDE];
__device__ float g_v[SEQ * KSTRIDE];
__device__ float g_ao[SEQ * QSTRIDE];

// ---------------------------------------------------------------------------
// packed f32x2 helpers (2x fp32 FMA throughput vs scalar 3-reg FFMA)
// ---------------------------------------------------------------------------
__device__ __forceinline__ ull ffma2(ull a, ull b, ull c) {
    ull d; asm("fma.rn.f32x2 %0, %1, %2, %3;" : "=l"(d) : "l"(a), "l"(b), "l"(c));
    return d;
}
__device__ __forceinline__ ull fmul2(ull a, ull b) {
    ull d; asm("mul.rn.f32x2 %0, %1, %2;" : "=l"(d) : "l"(a), "l"(b));
    return d;
}
__device__ __forceinline__ ull fadd2(ull a, ull b) {
    ull d; asm("add.rn.f32x2 %0, %1, %2;" : "=l"(d) : "l"(a), "l"(b));
    return d;
}
__device__ __forceinline__ ull pack2(float lo, float hi) {
    ull r; asm("mov.b64 %0, {%1, %2};" : "=l"(r) : "f"(lo), "f"(hi));
    return r;
}
__device__ __forceinline__ void unpack2(ull v, float& lo, float& hi) {
    asm("mov.b64 {%0, %1}, %2;" : "=f"(lo), "=f"(hi) : "l"(v));
}

// ---------------------------------------------------------------------------
// SGEMM core (packed f32x2): C[m,n] = sum_k X[m*K+k]*W[n*K+k] + bias[n]
// 128x128 tile, BK=8, 256 threads, 8x8 per-thread microtile.
// A is stored DUPLICATED-PACKED in smem: As2[k][row] = (a, a), so the packed
// multiplier operand is a straight LDS.128. B pairs come free from memory
// adjacency.
// ---------------------------------------------------------------------------
struct GemmSmem {
    ull   As2[8][128];   // 8 KB
    float Bs[8][128];    // 4 KB
};

__device__ __forceinline__ void gemm_tile_128(
    const float* __restrict__ X, const float* __restrict__ Wblk,
    const float* __restrict__ biasblk, float* __restrict__ Cblk,
    int ldc, int m0, int K, GemmSmem& sm)
{
    const int tid = threadIdx.x;
    const int tx = tid & 15;        // 0..15 -> n microtile
    const int ty = tid >> 4;        // 0..15 -> m microtile
    const int lr = tid >> 1;        // load row 0..127
    const int lk = (tid & 1) * 4;   // load k offset 0 or 4

    const float* Aptr = X + (size_t)(m0 + lr) * K + lk;
    const float* Bptr = Wblk + (size_t)lr * K + lk;

    float4 a_pf = *(const float4*)Aptr;
    float4 b_pf = *(const float4*)Bptr;

    ull acc2[8][4];
    #pragma unroll
    for (int i = 0; i < 8; i++)
        #pragma unroll
        for (int j = 0; j < 4; j++) acc2[i][j] = 0ull;

    const int nt = K >> 3;
    for (int kt = 0; kt < nt; kt++) {
        sm.As2[lk + 0][lr] = pack2(a_pf.x, a_pf.x);
        sm.As2[lk + 1][lr] = pack2(a_pf.y, a_pf.y);
        sm.As2[lk + 2][lr] = pack2(a_pf.z, a_pf.z);
        sm.As2[lk + 3][lr] = pack2(a_pf.w, a_pf.w);
        sm.Bs[lk + 0][lr] = b_pf.x;
        sm.Bs[lk + 1][lr] = b_pf.y;
        sm.Bs[lk + 2][lr] = b_pf.z;
        sm.Bs[lk + 3][lr] = b_pf.w;
        __syncthreads();

        if (kt + 1 < nt) {
            a_pf = *(const float4*)(Aptr + (kt + 1) * 8);
            b_pf = *(const float4*)(Bptr + (kt + 1) * 8);
        }

        #pragma unroll
        for (int kk = 0; kk < 8; kk++) {
            const ulonglong2* ap = (const ulonglong2*)&sm.As2[kk][ty * 8];
            ulonglong2 aa0 = ap[0], aa1 = ap[1], aa2 = ap[2], aa3 = ap[3];
            ulonglong2 b01 = *(const ulonglong2*)&sm.Bs[kk][tx * 8];
            ulonglong2 b23 = *(const ulonglong2*)&sm.Bs[kk][tx * 8 + 4];
            ull av[8];
            av[0] = aa0.x; av[1] = aa0.y; av[2] = aa1.x; av[3] = aa1.y;
            av[4] = aa2.x; av[5] = aa2.y; av[6] = aa3.x; av[7] = aa3.y;
            #pragma unroll
            for (int i = 0; i < 8; i++) {
                acc2[i][0] = ffma2(av[i], b01.x, acc2[i][0]);
                acc2[i][1] = ffma2(av[i], b01.y, acc2[i][1]);
                acc2[i][2] = ffma2(av[i], b23.x, acc2[i][2]);
                acc2[i][3] = ffma2(av[i], b23.y, acc2[i][3]);
            }
        }
        __syncthreads();
    }

    // epilogue: packed bias add, 128-bit stores
    ulonglong2 bv01 = *(const ulonglong2*)&biasblk[tx * 8];
    ulonglong2 bv23 = *(const ulonglong2*)&biasblk[tx * 8 + 4];
    #pragma unroll
    for (int i = 0; i < 8; i++) {
        float* crow = Cblk + (size_t)(m0 + ty * 8 + i) * ldc + tx * 8;
        ulonglong2 o01, o23;
        o01.x = fadd2(acc2[i][0], bv01.x);
        o01.y = fadd2(acc2[i][1], bv01.y);
        o23.x = fadd2(acc2[i][2], bv23.x);
        o23.y = fadd2(acc2[i][3], bv23.y);
        *(ulonglong2*)(crow + 0) = o01;
        *(ulonglong2*)(crow + 4) = o23;
    }
}

// ---------------------------------------------------------------------------
// Fused QKV projection. grid = (24, 16)
// ---------------------------------------------------------------------------
__global__ void __launch_bounds__(256) qkv_gemm_kernel(
    const float* __restrict__ x,
    const float* __restrict__ wq, const float* __restrict__ bq,
    const float* __restrict__ wk, const float* __restrict__ bk,
    const float* __restrict__ wv, const float* __restrict__ bv)
{
    __shared__ GemmSmem sm;
    const int nb = blockIdx.x;
    const int m0 = blockIdx.y * 128;
    if (nb < 16) {
        const int off = nb * 128;
        gemm_tile_128(x, wq + (size_t)off * DIM, bq + off, g_q + off,
                      QSTRIDE, m0, DIM, sm);
    } else if (nb < 20) {
        const int off = (nb - 16) * 128;
        gemm_tile_128(x, wk + (size_t)off * DIM, bk + off, g_k + off,
                      KSTRIDE, m0, DIM, sm);
    } else {
        const int off = (nb - 20) * 128;
        gemm_tile_128(x, wv + (size_t)off * DIM, bv + off, g_v + off,
                      KSTRIDE, m0, DIM, sm);
    }
}

// ---------------------------------------------------------------------------
// Output projection: out = g_ao @ wo^T + bo.  grid = (16, 16)
// ---------------------------------------------------------------------------
__global__ void __launch_bounds__(256) out_gemm_kernel(
    const float* __restrict__ wo, const float* __restrict__ bo,
    float* __restrict__ out)
{
    __shared__ GemmSmem sm;
    const int off = blockIdx.x * 128;
    gemm_tile_128(g_ao, wo + (size_t)off * DIM, bo + off, out + off,
                  DIM, blockIdx.y * 128, DIM, sm);
}

// ---------------------------------------------------------------------------
// RoPE (in place)
// ---------------------------------------------------------------------------
__global__ void rope_kernel(const float* __restrict__ rope, int is_q)
{
    float* buf = is_q ? g_q : g_k;
    const int nh = is_q ? NH : NKVH;
    const int total = SEQ * nh * 32;
    int idx = blockIdx.x * blockDim.x + threadIdx.x;
    if (idx >= total) return;
    const int d = idx & 31;
    const int h = (idx >> 5) % nh;
    const int s = idx / (32 * nh);
    const float c  = rope[s * 128 + d];
    const float sn = rope[s * 128 + 64 + d];
    float* row = buf + (size_t)s * (nh * HD) + h * HD;
    const float x0 = row[d];
    const float x1 = row[d + 32];
    row[d]      = x0 * c - x1 * sn;
    row[d + 32] = x1 * c + x0 * sn;
}

// ---------------------------------------------------------------------------
// Flash attention inner: one 64-key tile, keys in groups of 4 (ILP),
// packed f32x2 math. DIAG enables causal predication.
// ---------------------------------------------------------------------------
template<bool DIAG>
__device__ __forceinline__ void flash_block64(
    const float* __restrict__ Ks, const float* __restrict__ Vs,
    int base, int sq, const ull* q2, ull* acc2, float& m, float& l)
{
    #pragma unroll 1
    for (int kk = 0; kk < 64; kk += 4) {
        if (DIAG && base + kk > sq) break;
        float sc[4];
        #pragma unroll
        for (int j = 0; j < 4; j++) {
            const ulonglong2* kr = (const ulonglong2*)(Ks + (kk + j) * 64);
            ull s0 = 0ull, s1 = 0ull, s2 = 0ull, s3 = 0ull;
            #pragma unroll
            for (int d = 0; d < 16; d += 4) {
                ulonglong2 ka = kr[d + 0];
                ulonglong2 kb = kr[d + 1];
                ulonglong2 kc = kr[d + 2];
                ulonglong2 kd = kr[d + 3];
                s0 = ffma2(q2[2*d + 0], ka.x, s0);
                s1 = ffma2(q2[2*d + 1], ka.y, s1);
                s2 = ffma2(q2[2*d + 2], kb.x, s2);
                s3 = ffma2(q2[2*d + 3], kb.y, s3);
                s0 = ffma2(q2[2*d + 4], kc.x, s0);
                s1 = ffma2(q2[2*d + 5], kc.y, s1);
                s2 = ffma2(q2[2*d + 6], kd.x, s2);
                s3 = ffma2(q2[2*d + 7], kd.y, s3);
            }
            s0 = fadd2(s0, s1);
            s2 = fadd2(s2, s3);
            s0 = fadd2(s0, s2);
            float lo, hi; unpack2(s0, lo, hi);
            float v = lo + hi;
            if (DIAG && (base + kk + j > sq)) v = -1e30f;
            sc[j] = v;
        }
        const float mg = fmaxf(fmaxf(sc[0], sc[1]), fmaxf(sc[2], sc[3]));
        if (mg > m) {
            const float corr = __expf(m - mg);   // m = -inf first time -> 0
            l *= corr;
            const ull corr2 = pack2(corr, corr);
            #pragma unroll
            for (int d = 0; d < 32; d++) acc2[d] = fmul2(acc2[d], corr2);
            m = mg;
        }
        #pragma unroll
        for (int j = 0; j < 4; j++) {
            const float p = __expf(sc[j] - m);
            l += p;
            const ull p2 = pack2(p, p);
            const ulonglong2* vr = (const ulonglong2*)(Vs + (kk + j) * 64);
            #pragma unroll
            for (int d = 0; d < 16; d += 2) {
                ulonglong2 va = vr[d], vb = vr[d + 1];
                acc2[2*d + 0] = ffma2(p2, va.x, acc2[2*d + 0]);
                acc2[2*d + 1] = ffma2(p2, va.y, acc2[2*d + 1]);
                acc2[2*d + 2] = ffma2(p2, vb.x, acc2[2*d + 2]);
                acc2[2*d + 3] = ffma2(p2, vb.y, acc2[2*d + 3]);
            }
        }
    }
}

__device__ __forceinline__ void flash_one(
    int q0, int h, int kvh, const float* __restrict__ sinks,
    float (*Ks)[64], float (*Vs)[64])
{
    const int tid = threadIdx.x;
    const int sq = q0 + tid;

    ull q2[32];
    {
        const float* qrow = g_q + (size_t)sq * QSTRIDE + h * HD;
        #pragma unroll
        for (int d4 = 0; d4 < 16; d4++) {
            float4 qv = *(const float4*)(qrow + d4 * 4);
            q2[2*d4 + 0] = pack2(qv.x * 0.125f, qv.y * 0.125f);
            q2[2*d4 + 1] = pack2(qv.z * 0.125f, qv.w * 0.125f);
        }
    }
    ull acc2[32];
    #pragma unroll
    for (int d = 0; d < 32; d++) acc2[d] = 0ull;
    float m = -INFINITY, l = 0.f;

    const int nfull = q0 >> 6;                 // tiles fully below diagonal
    for (int t = 0; t < nfull + 2; t++) {
        const int base = t * 64;
        #pragma unroll
        for (int i = 0; i < 8; i++) {
            const int lin = tid + i * 128;
            const int r  = lin >> 4;
            const int c4 = (lin & 15) << 2;
            const size_t goff = (size_t)(base + r) * KSTRIDE + kvh * HD + c4;
            *(float4*)&Ks[r][c4] = *(const float4*)(g_k + goff);
            *(float4*)&Vs[r][c4] = *(const float4*)(g_v + goff);
        }
        __syncthreads();
        if (t < nfull)
            flash_block64<false>(&Ks[0][0], &Vs[0][0], base, sq, q2, acc2, m, l);
        else
            flash_block64<true>(&Ks[0][0], &Vs[0][0], base, sq, q2, acc2, m, l);
        __syncthreads();
    }

    // sink-token LSE renormalization
    const float lse = m + __logf(l);
    const float sk  = sinks[h];
    const float dmax = fmaxf(lse, sk);
    const float combined = dmax + log1pf(__expf(-fabsf(lse - sk)));
    const float r = __expf(fmaxf(lse - combined, -20.f));
    const float inv = r / l;
    const ull inv2 = pack2(inv, inv);

    float* orow = g_ao + (size_t)sq * QSTRIDE + h * HD;
    #pragma unroll
    for (int d = 0; d < 32; d += 2) {
        ulonglong2 o;
        o.x = fmul2(acc2[d], inv2);
        o.y = fmul2(acc2[d + 1], inv2);
        *(ulonglong2*)(orow + 2 * d) = o;
    }
}

// grid = (8, NH), 128 threads. Each block processes q-tiles bx and 15-bx
// (uniform 34 kv-tile loads per block -> balanced single wave of 256 blocks).
__global__ void __launch_bounds__(128) flash_kernel(
    const float* __restrict__ sinks)
{
    __shared__ float Ks[64][64];
    __shared__ float Vs[64][64];
    const int h   = blockIdx.y;
    const int kvh = h >> 2;               // REP = 4

    flash_one(blockIdx.x * 128, h, kvh, sinks, Ks, Vs);
    __syncthreads();
    flash_one((15 - blockIdx.x) * 128, h, kvh, sinks, Ks, Vs);
}

// ---------------------------------------------------------------------------
extern "C" void kernel_launch(void* const* d_in, const int* in_sizes, int n_in,
                              void* d_out, int out_size)
{
    const float* x     = (const float*)d_in[0];
    const float* rope  = (const float*)d_in[1];
    const float* wq    = (const float*)d_in[2];
    const float* bq    = (const float*)d_in[3];
    const float* wk    = (const float*)d_in[4];
    const float* bk    = (const float*)d_in[5];
    const float* wv    = (const float*)d_in[6];
    const float* bv    = (const float*)d_in[7];
    const float* wo    = (const float*)d_in[8];
    const float* bo    = (const float*)d_in[9];
    const float* sinks = (const float*)d_in[10];
    float* out = (float*)d_out;

    // 1) fused QKV projection
    qkv_gemm_kernel<<<dim3(24, 16), 256>>>(x, wq, bq, wk, bk, wv, bv);

    // 2) RoPE on q and k
    {
        const int tq = SEQ * NH * 32;
        rope_kernel<<<(tq + 255) / 256, 256>>>(rope, 1);
        const int tk = SEQ * NKVH * 32;
        rope_kernel<<<(tk + 255) / 256, 256>>>(rope, 0);
    }

    // 3) causal flash attention + sink renorm (balanced pairing)
    flash_kernel<<<dim3(8, NH), 128>>>(sinks);

    // 4) output projection
    out_gemm_kernel<<<dim3(16, 16), 256>>>(wo, bo, out);
}

// round 11
// speedup vs baseline: 1.2023x; 1.2023x over previous
#include <cuda_runtime.h>
#include <math.h>

#define SEQ 2048
#define DIM 2048
#define NH 32
#define NKVH 8
#define HD 64
#define QSTRIDE (NH*HD)     // 2048
#define KSTRIDE (NKVH*HD)   // 512

typedef unsigned long long ull;

// scratch (device globals: no allocation allowed)
__device__ float g_q[SEQ * QSTRIDE];
__device__ float g_k[SEQ * KSTRIDE];
__device__ float g_v[SEQ * KSTRIDE];
__device__ float g_ao[SEQ * QSTRIDE];

// ---------------------------------------------------------------------------
// packed f32x2 helpers
// ---------------------------------------------------------------------------
__device__ __forceinline__ ull ffma2(ull a, ull b, ull c) {
    ull d; asm("fma.rn.f32x2 %0, %1, %2, %3;" : "=l"(d) : "l"(a), "l"(b), "l"(c));
    return d;
}
__device__ __forceinline__ ull fmul2(ull a, ull b) {
    ull d; asm("mul.rn.f32x2 %0, %1, %2;" : "=l"(d) : "l"(a), "l"(b));
    return d;
}
__device__ __forceinline__ ull fadd2(ull a, ull b) {
    ull d; asm("add.rn.f32x2 %0, %1, %2;" : "=l"(d) : "l"(a), "l"(b));
    return d;
}
__device__ __forceinline__ ull pack2(float lo, float hi) {
    ull r; asm("mov.b64 %0, {%1, %2};" : "=l"(r) : "f"(lo), "f"(hi));
    return r;
}
__device__ __forceinline__ void unpack2(ull v, float& lo, float& hi) {
    asm("mov.b64 {%0, %1}, %2;" : "=f"(lo), "=f"(hi) : "l"(v));
}

// ---------------------------------------------------------------------------
// SGEMM core (scalar FFMA — proven at the fp32 pipe ceiling ~40 TF):
// C[m, n] = sum_k X[m*K+k] * W[n*K+k] + bias[n]
// 128x128 tile, BK=8, 256 threads, 8x8 per-thread microtile, reg prefetch.
// ---------------------------------------------------------------------------
struct GemmSmem {
    float As[8][128];
    float Bs[8][128];
};

__device__ __forceinline__ void gemm_tile_128(
    const float* __restrict__ X, const float* __restrict__ Wblk,
    const float* __restrict__ biasblk, float* __restrict__ Cblk,
    int ldc, int m0, int K, GemmSmem& sm)
{
    const int tid = threadIdx.x;
    const int tx = tid & 15;        // 0..15 -> n microtile
    const int ty = tid >> 4;        // 0..15 -> m microtile
    const int lr = tid >> 1;        // load row 0..127
    const int lk = (tid & 1) * 4;   // load k offset 0 or 4

    const float* Aptr = X + (size_t)(m0 + lr) * K + lk;
    const float* Bptr = Wblk + (size_t)lr * K + lk;

    float4 a_pf = *(const float4*)Aptr;
    float4 b_pf = *(const float4*)Bptr;

    float acc[8][8];
    #pragma unroll
    for (int i = 0; i < 8; i++)
        #pragma unroll
        for (int j = 0; j < 8; j++) acc[i][j] = 0.f;

    const int nt = K >> 3;
    for (int kt = 0; kt < nt; kt++) {
        sm.As[lk + 0][lr] = a_pf.x;
        sm.As[lk + 1][lr] = a_pf.y;
        sm.As[lk + 2][lr] = a_pf.z;
        sm.As[lk + 3][lr] = a_pf.w;
        sm.Bs[lk + 0][lr] = b_pf.x;
        sm.Bs[lk + 1][lr] = b_pf.y;
        sm.Bs[lk + 2][lr] = b_pf.z;
        sm.Bs[lk + 3][lr] = b_pf.w;
        __syncthreads();

        if (kt + 1 < nt) {
            a_pf = *(const float4*)(Aptr + (kt + 1) * 8);
            b_pf = *(const float4*)(Bptr + (kt + 1) * 8);
        }

        #pragma unroll
        for (int kk = 0; kk < 8; kk++) {
            float af[8], bf[8];
            *(float4*)(af + 0) = *(const float4*)&sm.As[kk][ty * 8 + 0];
            *(float4*)(af + 4) = *(const float4*)&sm.As[kk][ty * 8 + 4];
            *(float4*)(bf + 0) = *(const float4*)&sm.Bs[kk][tx * 8 + 0];
            *(float4*)(bf + 4) = *(const float4*)&sm.Bs[kk][tx * 8 + 4];
            #pragma unroll
            for (int i = 0; i < 8; i++)
                #pragma unroll
                for (int j = 0; j < 8; j++)
                    acc[i][j] = fmaf(af[i], bf[j], acc[i][j]);
        }
        __syncthreads();
    }

    // epilogue: add bias, vector store
    float bv[8];
    #pragma unroll
    for (int j = 0; j < 8; j++) bv[j] = biasblk[tx * 8 + j];

    #pragma unroll
    for (int i = 0; i < 8; i++) {
        float* crow = Cblk + (size_t)(m0 + ty * 8 + i) * ldc + tx * 8;
        float4 o0, o1;
        o0.x = acc[i][0] + bv[0]; o0.y = acc[i][1] + bv[1];
        o0.z = acc[i][2] + bv[2]; o0.w = acc[i][3] + bv[3];
        o1.x = acc[i][4] + bv[4]; o1.y = acc[i][5] + bv[5];
        o1.z = acc[i][6] + bv[6]; o1.w = acc[i][7] + bv[7];
        *(float4*)(crow + 0) = o0;
        *(float4*)(crow + 4) = o1;
    }
}

// ---------------------------------------------------------------------------
// Fused QKV projection. grid = (24, 16)
// ---------------------------------------------------------------------------
__global__ void __launch_bounds__(256) qkv_gemm_kernel(
    const float* __restrict__ x,
    const float* __restrict__ wq, const float* __restrict__ bq,
    const float* __restrict__ wk, const float* __restrict__ bk,
    const float* __restrict__ wv, const float* __restrict__ bv)
{
    __shared__ GemmSmem sm;
    const int nb = blockIdx.x;
    const int m0 = blockIdx.y * 128;
    if (nb < 16) {
        const int off = nb * 128;
        gemm_tile_128(x, wq + (size_t)off * DIM, bq + off, g_q + off,
                      QSTRIDE, m0, DIM, sm);
    } else if (nb < 20) {
        const int off = (nb - 16) * 128;
        gemm_tile_128(x, wk + (size_t)off * DIM, bk + off, g_k + off,
                      KSTRIDE, m0, DIM, sm);
    } else {
        const int off = (nb - 20) * 128;
        gemm_tile_128(x, wv + (size_t)off * DIM, bv + off, g_v + off,
                      KSTRIDE, m0, DIM, sm);
    }
}

// ---------------------------------------------------------------------------
// Output projection: out = g_ao @ wo^T + bo.  grid = (16, 16)
// ---------------------------------------------------------------------------
__global__ void __launch_bounds__(256) out_gemm_kernel(
    const float* __restrict__ wo, const float* __restrict__ bo,
    float* __restrict__ out)
{
    __shared__ GemmSmem sm;
    const int off = blockIdx.x * 128;
    gemm_tile_128(g_ao, wo + (size_t)off * DIM, bo + off, out + off,
                  DIM, blockIdx.y * 128, DIM, sm);
}

// ---------------------------------------------------------------------------
// RoPE (in place)
// ---------------------------------------------------------------------------
__global__ void rope_kernel(const float* __restrict__ rope, int is_q)
{
    float* buf = is_q ? g_q : g_k;
    const int nh = is_q ? NH : NKVH;
    const int total = SEQ * nh * 32;
    int idx = blockIdx.x * blockDim.x + threadIdx.x;
    if (idx >= total) return;
    const int d = idx & 31;
    const int h = (idx >> 5) % nh;
    const int s = idx / (32 * nh);
    const float c  = rope[s * 128 + d];
    const float sn = rope[s * 128 + 64 + d];
    float* row = buf + (size_t)s * (nh * HD) + h * HD;
    const float x0 = row[d];
    const float x1 = row[d + 32];
    row[d]      = x0 * c - x1 * sn;
    row[d + 32] = x1 * c + x0 * sn;
}

// ---------------------------------------------------------------------------
// Flash attention inner: one 64-key tile, keys in groups of 4 (ILP),
// packed f32x2 math. DIAG enables causal predication.
// Non-DIAG path allows unroll 2 across key groups so the scheduler can
// overlap group j's V-accumulation with group j+1's QK dot products.
// ---------------------------------------------------------------------------
template<bool DIAG>
__device__ __forceinline__ void flash_block64(
    const float* __restrict__ Ks, const float* __restrict__ Vs,
    int base, int sq, const ull* q2, ull* acc2, float& m, float& l)
{
    #pragma unroll 1
    for (int kk0 = 0; kk0 < 64; kk0 += (DIAG ? 4 : 8)) {
        if (DIAG && base + kk0 > sq) break;
        #pragma unroll
        for (int g = 0; g < (DIAG ? 1 : 2); g++) {
            const int kk = kk0 + g * 4;
            float sc[4];
            #pragma unroll
            for (int j = 0; j < 4; j++) {
                const ulonglong2* kr = (const ulonglong2*)(Ks + (kk + j) * 64);
                ull s0 = 0ull, s1 = 0ull, s2 = 0ull, s3 = 0ull;
                #pragma unroll
                for (int d = 0; d < 16; d += 4) {
                    ulonglong2 ka = kr[d + 0];
                    ulonglong2 kb = kr[d + 1];
                    ulonglong2 kc = kr[d + 2];
                    ulonglong2 kd = kr[d + 3];
                    s0 = ffma2(q2[2*d + 0], ka.x, s0);
                    s1 = ffma2(q2[2*d + 1], ka.y, s1);
                    s2 = ffma2(q2[2*d + 2], kb.x, s2);
                    s3 = ffma2(q2[2*d + 3], kb.y, s3);
                    s0 = ffma2(q2[2*d + 4], kc.x, s0);
                    s1 = ffma2(q2[2*d + 5], kc.y, s1);
                    s2 = ffma2(q2[2*d + 6], kd.x, s2);
                    s3 = ffma2(q2[2*d + 7], kd.y, s3);
                }
                s0 = fadd2(s0, s1);
                s2 = fadd2(s2, s3);
                s0 = fadd2(s0, s2);
                float lo, hi; unpack2(s0, lo, hi);
                float v = lo + hi;
                if (DIAG && (base + kk + j > sq)) v = -1e30f;
                sc[j] = v;
            }
            const float mg = fmaxf(fmaxf(sc[0], sc[1]), fmaxf(sc[2], sc[3]));
            if (mg > m) {                       // lazy rescale (rare)
                const float corr = __expf(m - mg);   // m=-inf first time -> 0
                l *= corr;
                const ull corr2 = pack2(corr, corr);
                #pragma unroll
                for (int d = 0; d < 32; d++) acc2[d] = fmul2(acc2[d], corr2);
                m = mg;
            }
            // 4 independent exps; shortened l-chain (pairwise sum, one add)
            float p[4];
            #pragma unroll
            for (int j = 0; j < 4; j++) p[j] = __expf(sc[j] - m);
            l += (p[0] + p[1]) + (p[2] + p[3]);
            #pragma unroll
            for (int j = 0; j < 4; j++) {
                const ull p2 = pack2(p[j], p[j]);
                const ulonglong2* vr = (const ulonglong2*)(Vs + (kk + j) * 64);
                #pragma unroll
                for (int d = 0; d < 16; d += 2) {
                    ulonglong2 va = vr[d], vb = vr[d + 1];
                    acc2[2*d + 0] = ffma2(p2, va.x, acc2[2*d + 0]);
                    acc2[2*d + 1] = ffma2(p2, va.y, acc2[2*d + 1]);
                    acc2[2*d + 2] = ffma2(p2, vb.x, acc2[2*d + 2]);
                    acc2[2*d + 3] = ffma2(p2, vb.y, acc2[2*d + 3]);
                }
            }
        }
    }
}

__device__ __forceinline__ void flash_one(
    int q0, int h, int kvh, const float* __restrict__ sinks,
    float (*Ks)[64], float (*Vs)[64])
{
    const int tid = threadIdx.x;
    const int sq = q0 + tid;

    ull q2[32];
    {
        const float* qrow = g_q + (size_t)sq * QSTRIDE + h * HD;
        #pragma unroll
        for (int d4 = 0; d4 < 16; d4++) {
            float4 qv = *(const float4*)(qrow + d4 * 4);
            q2[2*d4 + 0] = pack2(qv.x * 0.125f, qv.y * 0.125f);
            q2[2*d4 + 1] = pack2(qv.z * 0.125f, qv.w * 0.125f);
        }
    }
    ull acc2[32];
    #pragma unroll
    for (int d = 0; d < 32; d++) acc2[d] = 0ull;
    float m = -INFINITY, l = 0.f;

    const int nfull = q0 >> 6;                 // tiles fully below diagonal
    for (int t = 0; t < nfull + 2; t++) {
        const int base = t * 64;
        #pragma unroll
        for (int i = 0; i < 8; i++) {
            const int lin = tid + i * 128;
            const int r  = lin >> 4;
            const int c4 = (lin & 15) << 2;
            const size_t goff = (size_t)(base + r) * KSTRIDE + kvh * HD + c4;
            *(float4*)&Ks[r][c4] = *(const float4*)(g_k + goff);
            *(float4*)&Vs[r][c4] = *(const float4*)(g_v + goff);
        }
        __syncthreads();
        if (t < nfull)
            flash_block64<false>(&Ks[0][0], &Vs[0][0], base, sq, q2, acc2, m, l);
        else
            flash_block64<true>(&Ks[0][0], &Vs[0][0], base, sq, q2, acc2, m, l);
        __syncthreads();
    }

    // sink-token LSE renormalization
    const float lse = m + __logf(l);
    const float sk  = sinks[h];
    const float dmax = fmaxf(lse, sk);
    const float combined = dmax + log1pf(__expf(-fabsf(lse - sk)));
    const float r = __expf(fmaxf(lse - combined, -20.f));
    const float inv = r / l;
    const ull inv2 = pack2(inv, inv);

    float* orow = g_ao + (size_t)sq * QSTRIDE + h * HD;
    #pragma unroll
    for (int d = 0; d < 32; d += 2) {
        ulonglong2 o;
        o.x = fmul2(acc2[d], inv2);
        o.y = fmul2(acc2[d + 1], inv2);
        *(ulonglong2*)(orow + 2 * d) = o;
    }
}

// grid = (8, NH), 128 threads. Each block processes q-tiles bx and 15-bx
// (uniform 34 kv-tile loads per block -> balanced single wave of 256 blocks).
__global__ void __launch_bounds__(128) flash_kernel(
    const float* __restrict__ sinks)
{
    __shared__ float Ks[64][64];
    __shared__ float Vs[64][64];
    const int h   = blockIdx.y;
    const int kvh = h >> 2;               // REP = 4

    flash_one(blockIdx.x * 128, h, kvh, sinks, Ks, Vs);
    __syncthreads();
    flash_one((15 - blockIdx.x) * 128, h, kvh, sinks, Ks, Vs);
}

// ---------------------------------------------------------------------------
extern "C" void kernel_launch(void* const* d_in, const int* in_sizes, int n_in,
                              void* d_out, int out_size)
{
    const float* x     = (const float*)d_in[0];
    const float* rope  = (const float*)d_in[1];
    const float* wq    = (const float*)d_in[2];
    const float* bq    = (const float*)d_in[3];
    const float* wk    = (const float*)d_in[4];
    const float* bk    = (const float*)d_in[5];
    const float* wv    = (const float*)d_in[6];
    const float* bv    = (const float*)d_in[7];
    const float* wo    = (const float*)d_in[8];
    const float* bo    = (const float*)d_in[9];
    const float* sinks = (const float*)d_in[10];
    float* out = (float*)d_out;

    // 1) fused QKV projection (scalar FFMA core — at fp32 pipe ceiling)
    qkv_gemm_kernel<<<dim3(24, 16), 256>>>(x, wq, bq, wk, bk, wv, bv);

    // 2) RoPE on q and k
    {
        const int tq = SEQ * NH * 32;
        rope_kernel<<<(tq + 255) / 256, 256>>>(rope, 1);
        const int tk = SEQ * NKVH * 32;
        rope_kernel<<<(tk + 255) / 256, 256>>>(rope, 0);
    }

    // 3) causal flash attention + sink renorm (balanced pairing)
    flash_kernel<<<dim3(8, NH), 128>>>(sinks);

    // 4) output projection
    out_gemm_kernel<<<dim3(16, 16), 256>>>(wo, bo, out);
}

// round 12
// speedup vs baseline: 1.8973x; 1.5780x over previous
#include <cuda_runtime.h>
#include <cuda_bf16.h>
#include <math.h>

#define SEQ 2048
#define DIM 2048
#define NH 32
#define NKVH 8
#define HD 64
#define QSTRIDE (NH*HD)     // 2048
#define KSTRIDE (NKVH*HD)   // 512

typedef unsigned long long ull;

// scratch (device globals: no allocation allowed)
__device__ float g_q[SEQ * QSTRIDE];
__device__ float g_k[SEQ * KSTRIDE];
__device__ float g_v[SEQ * KSTRIDE];
__device__ float g_ao[SEQ * QSTRIDE];

// ---------------------------------------------------------------------------
// packed f32x2 helpers (flash kernel)
// ---------------------------------------------------------------------------
__device__ __forceinline__ ull ffma2(ull a, ull b, ull c) {
    ull d; asm("fma.rn.f32x2 %0, %1, %2, %3;" : "=l"(d) : "l"(a), "l"(b), "l"(c));
    return d;
}
__device__ __forceinline__ ull fmul2(ull a, ull b) {
    ull d; asm("mul.rn.f32x2 %0, %1, %2;" : "=l"(d) : "l"(a), "l"(b));
    return d;
}
__device__ __forceinline__ ull fadd2(ull a, ull b) {
    ull d; asm("add.rn.f32x2 %0, %1, %2;" : "=l"(d) : "l"(a), "l"(b));
    return d;
}
__device__ __forceinline__ ull pack2(float lo, float hi) {
    ull r; asm("mov.b64 %0, {%1, %2};" : "=l"(r) : "f"(lo), "f"(hi));
    return r;
}
__device__ __forceinline__ void unpack2(ull v, float& lo, float& hi) {
    asm("mov.b64 {%0, %1}, %2;" : "=f"(lo), "=f"(hi) : "l"(v));
}

// ---------------------------------------------------------------------------
// Tensor-core GEMM (bf16 split-3): C[m,n] = sum_k X[m*K+k]*W[n*K+k] + bias[n]
// x = hi + lo (bf16 each); x*y ~= hi*hi + hi*lo + lo*hi  (error ~2^-17)
// 128x128 tile, BK=32, 256 threads / 8 warps, warp tile 64x32.
// smem pitch 40 bf16 (20 words) -> conflict-free m16n8k16 fragment loads.
// ---------------------------------------------------------------------------
struct MmaSmem {
    __nv_bfloat16 Ah[128][40];
    __nv_bfloat16 Al[128][40];
    __nv_bfloat16 Bh[128][40];
    __nv_bfloat16 Bl[128][40];
};  // 40960 bytes

__device__ __forceinline__ void mma16816(float* d, const unsigned* a, const unsigned* b) {
    asm volatile(
        "mma.sync.aligned.m16n8k16.row.col.f32.bf16.bf16.f32 "
        "{%0,%1,%2,%3}, {%4,%5,%6,%7}, {%8,%9}, {%0,%1,%2,%3};"
        : "+f"(d[0]), "+f"(d[1]), "+f"(d[2]), "+f"(d[3])
        : "r"(a[0]), "r"(a[1]), "r"(a[2]), "r"(a[3]), "r"(b[0]), "r"(b[1]));
}

__device__ __forceinline__ void split4(float4 v, unsigned& h01, unsigned& h23,
                                       unsigned& l01, unsigned& l23) {
    __nv_bfloat16 hx = __float2bfloat16_rn(v.x);
    __nv_bfloat16 hy = __float2bfloat16_rn(v.y);
    __nv_bfloat16 hz = __float2bfloat16_rn(v.z);
    __nv_bfloat16 hw = __float2bfloat16_rn(v.w);
    __nv_bfloat162 hp0 = __halves2bfloat162(hx, hy);
    __nv_bfloat162 hp1 = __halves2bfloat162(hz, hw);
    __nv_bfloat162 lp0 = __halves2bfloat162(
        __float2bfloat16_rn(v.x - __bfloat162float(hx)),
        __float2bfloat16_rn(v.y - __bfloat162float(hy)));
    __nv_bfloat162 lp1 = __halves2bfloat162(
        __float2bfloat16_rn(v.z - __bfloat162float(hz)),
        __float2bfloat16_rn(v.w - __bfloat162float(hw)));
    h01 = *(unsigned*)&hp0; h23 = *(unsigned*)&hp1;
    l01 = *(unsigned*)&lp0; l23 = *(unsigned*)&lp1;
}

__device__ __forceinline__ void mma_tile_128(
    const float* __restrict__ X, const float* __restrict__ Wblk,
    const float* __restrict__ biasblk, float* __restrict__ Cblk,
    int ldc, int m0, int K, MmaSmem& sm)
{
    const int tid  = threadIdx.x;
    const int lane = tid & 31;
    const int wid  = tid >> 5;       // 0..7
    const int wm   = wid & 1;        // m half (64 rows)
    const int wn   = wid >> 1;       // n quarter (32 cols)

    float acc[4][4][4];
    #pragma unroll
    for (int i = 0; i < 4; i++)
        #pragma unroll
        for (int j = 0; j < 4; j++)
            #pragma unroll
            for (int c = 0; c < 4; c++) acc[i][j][c] = 0.f;

    // global-load mapping: lin = tid + i*256 -> r = lin>>3, kc = (lin&7)*4
    float4 apf[4], bpf[4];
    #pragma unroll
    for (int i = 0; i < 4; i++) {
        const int lin = tid + i * 256;
        const int r = lin >> 3, kc = (lin & 7) * 4;
        apf[i] = *(const float4*)&X[(size_t)(m0 + r) * K + kc];
        bpf[i] = *(const float4*)&Wblk[(size_t)r * K + kc];
    }

    const int nt = K >> 5;    // BK = 32
    for (int kt = 0; kt < nt; kt++) {
        // convert fp32 -> (hi, lo) bf16 and store to smem
        #pragma unroll
        for (int i = 0; i < 4; i++) {
            const int lin = tid + i * 256;
            const int r = lin >> 3, kc = (lin & 7) * 4;
            unsigned h01, h23, l01, l23;
            split4(apf[i], h01, h23, l01, l23);
            *(uint2*)&sm.Ah[r][kc] = make_uint2(h01, h23);
            *(uint2*)&sm.Al[r][kc] = make_uint2(l01, l23);
            split4(bpf[i], h01, h23, l01, l23);
            *(uint2*)&sm.Bh[r][kc] = make_uint2(h01, h23);
            *(uint2*)&sm.Bl[r][kc] = make_uint2(l01, l23);
        }
        __syncthreads();

        if (kt + 1 < nt) {
            const int kb = (kt + 1) * 32;
            #pragma unroll
            for (int i = 0; i < 4; i++) {
                const int lin = tid + i * 256;
                const int r = lin >> 3, kc = (lin & 7) * 4;
                apf[i] = *(const float4*)&X[(size_t)(m0 + r) * K + kb + kc];
                bpf[i] = *(const float4*)&Wblk[(size_t)r * K + kb + kc];
            }
        }

        #pragma unroll
        for (int ko = 0; ko < 2; ko++) {
            const int kc = ko * 16 + (lane & 3) * 2;
            unsigned bh[4][2], bl[4][2];
            #pragma unroll
            for (int j = 0; j < 4; j++) {
                const int bn = wn * 32 + j * 8 + (lane >> 2);
                bh[j][0] = *(unsigned*)&sm.Bh[bn][kc];
                bh[j][1] = *(unsigned*)&sm.Bh[bn][kc + 8];
                bl[j][0] = *(unsigned*)&sm.Bl[bn][kc];
                bl[j][1] = *(unsigned*)&sm.Bl[bn][kc + 8];
            }
            #pragma unroll
            for (int i = 0; i < 4; i++) {
                const int ar = wm * 64 + i * 16 + (lane >> 2);
                unsigned ah[4], al[4];
                ah[0] = *(unsigned*)&sm.Ah[ar][kc];
                ah[1] = *(unsigned*)&sm.Ah[ar + 8][kc];
                ah[2] = *(unsigned*)&sm.Ah[ar][kc + 8];
                ah[3] = *(unsigned*)&sm.Ah[ar + 8][kc + 8];
                al[0] = *(unsigned*)&sm.Al[ar][kc];
                al[1] = *(unsigned*)&sm.Al[ar + 8][kc];
                al[2] = *(unsigned*)&sm.Al[ar][kc + 8];
                al[3] = *(unsigned*)&sm.Al[ar + 8][kc + 8];
                #pragma unroll
                for (int j = 0; j < 4; j++) {
                    mma16816(acc[i][j], ah, bh[j]);   // hi*hi
                    mma16816(acc[i][j], ah, bl[j]);   // hi*lo
                    mma16816(acc[i][j], al, bh[j]);   // lo*hi
                }
            }
        }
        __syncthreads();
    }

    // epilogue: bias + store (float2, 8B aligned: col even)
    #pragma unroll
    for (int i = 0; i < 4; i++) {
        const int row = m0 + wm * 64 + i * 16 + (lane >> 2);
        #pragma unroll
        for (int j = 0; j < 4; j++) {
            const int col = wn * 32 + j * 8 + (lane & 3) * 2;
            const float2 bb = *(const float2*)&biasblk[col];
            float2 o0, o1;
            o0.x = acc[i][j][0] + bb.x; o0.y = acc[i][j][1] + bb.y;
            o1.x = acc[i][j][2] + bb.x; o1.y = acc[i][j][3] + bb.y;
            *(float2*)&Cblk[(size_t)row * ldc + col] = o0;
            *(float2*)&Cblk[(size_t)(row + 8) * ldc + col] = o1;
        }
    }
}

// ---------------------------------------------------------------------------
// Fused QKV projection. grid = (24, 16)
// ---------------------------------------------------------------------------
__global__ void __launch_bounds__(256, 1) qkv_gemm_kernel(
    const float* __restrict__ x,
    const float* __restrict__ wq, const float* __restrict__ bq,
    const float* __restrict__ wk, const float* __restrict__ bk,
    const float* __restrict__ wv, const float* __restrict__ bv)
{
    __shared__ MmaSmem sm;
    const int nb = blockIdx.x;
    const int m0 = blockIdx.y * 128;
    if (nb < 16) {
        const int off = nb * 128;
        mma_tile_128(x, wq + (size_t)off * DIM, bq + off, g_q + off,
                     QSTRIDE, m0, DIM, sm);
    } else if (nb < 20) {
        const int off = (nb - 16) * 128;
        mma_tile_128(x, wk + (size_t)off * DIM, bk + off, g_k + off,
                     KSTRIDE, m0, DIM, sm);
    } else {
        const int off = (nb - 20) * 128;
        mma_tile_128(x, wv + (size_t)off * DIM, bv + off, g_v + off,
                     KSTRIDE, m0, DIM, sm);
    }
}

// ---------------------------------------------------------------------------
// Output projection: out = g_ao @ wo^T + bo.  grid = (16, 16)
// ---------------------------------------------------------------------------
__global__ void __launch_bounds__(256, 1) out_gemm_kernel(
    const float* __restrict__ wo, const float* __restrict__ bo,
    float* __restrict__ out)
{
    __shared__ MmaSmem sm;
    const int off = blockIdx.x * 128;
    mma_tile_128(g_ao, wo + (size_t)off * DIM, bo + off, out + off,
                 DIM, blockIdx.y * 128, DIM, sm);
}

// ---------------------------------------------------------------------------
// RoPE (in place)
// ---------------------------------------------------------------------------
__global__ void rope_kernel(const float* __restrict__ rope, int is_q)
{
    float* buf = is_q ? g_q : g_k;
    const int nh = is_q ? NH : NKVH;
    const int total = SEQ * nh * 32;
    int idx = blockIdx.x * blockDim.x + threadIdx.x;
    if (idx >= total) return;
    const int d = idx & 31;
    const int h = (idx >> 5) % nh;
    const int s = idx / (32 * nh);
    const float c  = rope[s * 128 + d];
    const float sn = rope[s * 128 + 64 + d];
    float* row = buf + (size_t)s * (nh * HD) + h * HD;
    const float x0 = row[d];
    const float x1 = row[d + 32];
    row[d]      = x0 * c - x1 * sn;
    row[d + 32] = x1 * c + x0 * sn;
}

// ---------------------------------------------------------------------------
// Flash attention (unchanged from best-known 651us version)
// ---------------------------------------------------------------------------
template<bool DIAG>
__device__ __forceinline__ void flash_block64(
    const float* __restrict__ Ks, const float* __restrict__ Vs,
    int base, int sq, const ull* q2, ull* acc2, float& m, float& l)
{
    #pragma unroll 1
    for (int kk0 = 0; kk0 < 64; kk0 += (DIAG ? 4 : 8)) {
        if (DIAG && base + kk0 > sq) break;
        #pragma unroll
        for (int g = 0; g < (DIAG ? 1 : 2); g++) {
            const int kk = kk0 + g * 4;
            float sc[4];
            #pragma unroll
            for (int j = 0; j < 4; j++) {
                const ulonglong2* kr = (const ulonglong2*)(Ks + (kk + j) * 64);
                ull s0 = 0ull, s1 = 0ull, s2 = 0ull, s3 = 0ull;
                #pragma unroll
                for (int d = 0; d < 16; d += 4) {
                    ulonglong2 ka = kr[d + 0];
                    ulonglong2 kb = kr[d + 1];
                    ulonglong2 kc = kr[d + 2];
                    ulonglong2 kd = kr[d + 3];
                    s0 = ffma2(q2[2*d + 0], ka.x, s0);
                    s1 = ffma2(q2[2*d + 1], ka.y, s1);
                    s2 = ffma2(q2[2*d + 2], kb.x, s2);
                    s3 = ffma2(q2[2*d + 3], kb.y, s3);
                    s0 = ffma2(q2[2*d + 4], kc.x, s0);
                    s1 = ffma2(q2[2*d + 5], kc.y, s1);
                    s2 = ffma2(q2[2*d + 6], kd.x, s2);
                    s3 = ffma2(q2[2*d + 7], kd.y, s3);
                }
                s0 = fadd2(s0, s1);
                s2 = fadd2(s2, s3);
                s0 = fadd2(s0, s2);
                float lo, hi; unpack2(s0, lo, hi);
                float v = lo + hi;
                if (DIAG && (base + kk + j > sq)) v = -1e30f;
                sc[j] = v;
            }
            const float mg = fmaxf(fmaxf(sc[0], sc[1]), fmaxf(sc[2], sc[3]));
            if (mg > m) {                       // lazy rescale (rare)
                const float corr = __expf(m - mg);
                l *= corr;
                const ull corr2 = pack2(corr, corr);
                #pragma unroll
                for (int d = 0; d < 32; d++) acc2[d] = fmul2(acc2[d], corr2);
                m = mg;
            }
            float p[4];
            #pragma unroll
            for (int j = 0; j < 4; j++) p[j] = __expf(sc[j] - m);
            l += (p[0] + p[1]) + (p[2] + p[3]);
            #pragma unroll
            for (int j = 0; j < 4; j++) {
                const ull p2 = pack2(p[j], p[j]);
                const ulonglong2* vr = (const ulonglong2*)(Vs + (kk + j) * 64);
                #pragma unroll
                for (int d = 0; d < 16; d += 2) {
                    ulonglong2 va = vr[d], vb = vr[d + 1];
                    acc2[2*d + 0] = ffma2(p2, va.x, acc2[2*d + 0]);
                    acc2[2*d + 1] = ffma2(p2, va.y, acc2[2*d + 1]);
                    acc2[2*d + 2] = ffma2(p2, vb.x, acc2[2*d + 2]);
                    acc2[2*d + 3] = ffma2(p2, vb.y, acc2[2*d + 3]);
                }
            }
        }
    }
}

__device__ __forceinline__ void flash_one(
    int q0, int h, int kvh, const float* __restrict__ sinks,
    float (*Ks)[64], float (*Vs)[64])
{
    const int tid = threadIdx.x;
    const int sq = q0 + tid;

    ull q2[32];
    {
        const float* qrow = g_q + (size_t)sq * QSTRIDE + h * HD;
        #pragma unroll
        for (int d4 = 0; d4 < 16; d4++) {
            float4 qv = *(const float4*)(qrow + d4 * 4);
            q2[2*d4 + 0] = pack2(qv.x * 0.125f, qv.y * 0.125f);
            q2[2*d4 + 1] = pack2(qv.z * 0.125f, qv.w * 0.125f);
        }
    }
    ull acc2[32];
    #pragma unroll
    for (int d = 0; d < 32; d++) acc2[d] = 0ull;
    float m = -INFINITY, l = 0.f;

    const int nfull = q0 >> 6;
    for (int t = 0; t < nfull + 2; t++) {
        const int base = t * 64;
        #pragma unroll
        for (int i = 0; i < 8; i++) {
            const int lin = tid + i * 128;
            const int r  = lin >> 4;
            const int c4 = (lin & 15) << 2;
            const size_t goff = (size_t)(base + r) * KSTRIDE + kvh * HD + c4;
            *(float4*)&Ks[r][c4] = *(const float4*)(g_k + goff);
            *(float4*)&Vs[r][c4] = *(const float4*)(g_v + goff);
        }
        __syncthreads();
        if (t < nfull)
            flash_block64<false>(&Ks[0][0], &Vs[0][0], base, sq, q2, acc2, m, l);
        else
            flash_block64<true>(&Ks[0][0], &Vs[0][0], base, sq, q2, acc2, m, l);
        __syncthreads();
    }

    const float lse = m + __logf(l);
    const float sk  = sinks[h];
    const float dmax = fmaxf(lse, sk);
    const float combined = dmax + log1pf(__expf(-fabsf(lse - sk)));
    const float r = __expf(fmaxf(lse - combined, -20.f));
    const float inv = r / l;
    const ull inv2 = pack2(inv, inv);

    float* orow = g_ao + (size_t)sq * QSTRIDE + h * HD;
    #pragma unroll
    for (int d = 0; d < 32; d += 2) {
        ulonglong2 o;
        o.x = fmul2(acc2[d], inv2);
        o.y = fmul2(acc2[d + 1], inv2);
        *(ulonglong2*)(orow + 2 * d) = o;
    }
}

__global__ void __launch_bounds__(128) flash_kernel(
    const float* __restrict__ sinks)
{
    __shared__ float Ks[64][64];
    __shared__ float Vs[64][64];
    const int h   = blockIdx.y;
    const int kvh = h >> 2;               // REP = 4

    flash_one(blockIdx.x * 128, h, kvh, sinks, Ks, Vs);
    __syncthreads();
    flash_one((15 - blockIdx.x) * 128, h, kvh, sinks, Ks, Vs);
}

// ---------------------------------------------------------------------------
extern "C" void kernel_launch(void* const* d_in, const int* in_sizes, int n_in,
                              void* d_out, int out_size)
{
    const float* x     = (const float*)d_in[0];
    const float* rope  = (const float*)d_in[1];
    const float* wq    = (const float*)d_in[2];
    const float* bq    = (const float*)d_in[3];
    const float* wk    = (const float*)d_in[4];
    const float* bk    = (const float*)d_in[5];
    const float* wv    = (const float*)d_in[6];
    const float* bv    = (const float*)d_in[7];
    const float* wo    = (const float*)d_in[8];
    const float* bo    = (const float*)d_in[9];
    const float* sinks = (const float*)d_in[10];
    float* out = (float*)d_out;

    // 1) fused QKV projection (tensor core, bf16 split-3)
    qkv_gemm_kernel<<<dim3(24, 16), 256>>>(x, wq, bq, wk, bk, wv, bv);

    // 2) RoPE on q and k
    {
        const int tq = SEQ * NH * 32;
        rope_kernel<<<(tq + 255) / 256, 256>>>(rope, 1);
        const int tk = SEQ * NKVH * 32;
        rope_kernel<<<(tk + 255) / 256, 256>>>(rope, 0);
    }

    // 3) causal flash attention + sink renorm (balanced pairing)
    flash_kernel<<<dim3(8, NH), 128>>>(sinks);

    // 4) output projection (tensor core, bf16 split-3)
    out_gemm_kernel<<<dim3(16, 16), 256>>>(wo, bo, out);
}

// round 15
// speedup vs baseline: 3.0432x; 1.6040x over previous
#include <cuda_runtime.h>
#include <cuda_bf16.h>
#include <math.h>

#define SEQ 2048
#define DIM 2048
#define NH 32
#define NKVH 8
#define HD 64
#define QSTRIDE (NH*HD)     // 2048
#define KSTRIDE (NKVH*HD)   // 512

typedef unsigned long long ull;

// scratch (device globals: no allocation allowed)
__device__ float g_q[SEQ * QSTRIDE];
__device__ float g_k[SEQ * KSTRIDE];
__device__ float g_v[SEQ * KSTRIDE];
__device__ float g_ao[SEQ * QSTRIDE];

// ---------------------------------------------------------------------------
// mma + bf16 split helpers (conventions validated by the R12 GEMM)
// ---------------------------------------------------------------------------
__device__ __forceinline__ void mma16816(float* d, const unsigned* a, const unsigned* b) {
    asm volatile(
        "mma.sync.aligned.m16n8k16.row.col.f32.bf16.bf16.f32 "
        "{%0,%1,%2,%3}, {%4,%5,%6,%7}, {%8,%9}, {%0,%1,%2,%3};"
        : "+f"(d[0]), "+f"(d[1]), "+f"(d[2]), "+f"(d[3])
        : "r"(a[0]), "r"(a[1]), "r"(a[2]), "r"(a[3]), "r"(b[0]), "r"(b[1]));
}

__device__ __forceinline__ void split4(float4 v, unsigned& h01, unsigned& h23,
                                       unsigned& l01, unsigned& l23) {
    __nv_bfloat16 hx = __float2bfloat16_rn(v.x);
    __nv_bfloat16 hy = __float2bfloat16_rn(v.y);
    __nv_bfloat16 hz = __float2bfloat16_rn(v.z);
    __nv_bfloat16 hw = __float2bfloat16_rn(v.w);
    __nv_bfloat162 hp0 = __halves2bfloat162(hx, hy);
    __nv_bfloat162 hp1 = __halves2bfloat162(hz, hw);
    __nv_bfloat162 lp0 = __halves2bfloat162(
        __float2bfloat16_rn(v.x - __bfloat162float(hx)),
        __float2bfloat16_rn(v.y - __bfloat162float(hy)));
    __nv_bfloat162 lp1 = __halves2bfloat162(
        __float2bfloat16_rn(v.z - __bfloat162float(hz)),
        __float2bfloat16_rn(v.w - __bfloat162float(hw)));
    h01 = *(unsigned*)&hp0; h23 = *(unsigned*)&hp1;
    l01 = *(unsigned*)&lp0; l23 = *(unsigned*)&lp1;
}

__device__ __forceinline__ unsigned packbf(float a, float b) {
    __nv_bfloat162 t = __floats2bfloat162_rn(a, b);
    return *(unsigned*)&t;
}

// pack hi pair and lo pair (exact 2-term split of two floats)
__device__ __forceinline__ void packbf_hl(float a, float b,
                                          unsigned& hi, unsigned& lo) {
    __nv_bfloat16 ha = __float2bfloat16_rn(a);
    __nv_bfloat16 hb = __float2bfloat16_rn(b);
    __nv_bfloat162 hp = __halves2bfloat162(ha, hb);
    __nv_bfloat162 lp = __halves2bfloat162(
        __float2bfloat16_rn(a - __bfloat162float(ha)),
        __float2bfloat16_rn(b - __bfloat162float(hb)));
    hi = *(unsigned*)&hp;
    lo = *(unsigned*)&lp;
}

// ---------------------------------------------------------------------------
// Tensor-core GEMM (bf16 split-3) — unchanged from R12 (validated, ~430us)
// ---------------------------------------------------------------------------
struct MmaSmem {
    __nv_bfloat16 Ah[128][40];
    __nv_bfloat16 Al[128][40];
    __nv_bfloat16 Bh[128][40];
    __nv_bfloat16 Bl[128][40];
};

__device__ __forceinline__ void mma_tile_128(
    const float* __restrict__ X, const float* __restrict__ Wblk,
    const float* __restrict__ biasblk, float* __restrict__ Cblk,
    int ldc, int m0, int K, MmaSmem& sm)
{
    const int tid  = threadIdx.x;
    const int lane = tid & 31;
    const int wid  = tid >> 5;
    const int wm   = wid & 1;
    const int wn   = wid >> 1;

    float acc[4][4][4];
    #pragma unroll
    for (int i = 0; i < 4; i++)
        #pragma unroll
        for (int j = 0; j < 4; j++)
            #pragma unroll
            for (int c = 0; c < 4; c++) acc[i][j][c] = 0.f;

    float4 apf[4], bpf[4];
    #pragma unroll
    for (int i = 0; i < 4; i++) {
        const int lin = tid + i * 256;
        const int r = lin >> 3, kc = (lin & 7) * 4;
        apf[i] = *(const float4*)&X[(size_t)(m0 + r) * K + kc];
        bpf[i] = *(const float4*)&Wblk[(size_t)r * K + kc];
    }

    const int nt = K >> 5;
    for (int kt = 0; kt < nt; kt++) {
        #pragma unroll
        for (int i = 0; i < 4; i++) {
            const int lin = tid + i * 256;
            const int r = lin >> 3, kc = (lin & 7) * 4;
            unsigned h01, h23, l01, l23;
            split4(apf[i], h01, h23, l01, l23);
            *(uint2*)&sm.Ah[r][kc] = make_uint2(h01, h23);
            *(uint2*)&sm.Al[r][kc] = make_uint2(l01, l23);
            split4(bpf[i], h01, h23, l01, l23);
            *(uint2*)&sm.Bh[r][kc] = make_uint2(h01, h23);
            *(uint2*)&sm.Bl[r][kc] = make_uint2(l01, l23);
        }
        __syncthreads();

        if (kt + 1 < nt) {
            const int kb = (kt + 1) * 32;
            #pragma unroll
            for (int i = 0; i < 4; i++) {
                const int lin = tid + i * 256;
                const int r = lin >> 3, kc = (lin & 7) * 4;
                apf[i] = *(const float4*)&X[(size_t)(m0 + r) * K + kb + kc];
                bpf[i] = *(const float4*)&Wblk[(size_t)r * K + kb + kc];
            }
        }

        #pragma unroll
        for (int ko = 0; ko < 2; ko++) {
            const int kc = ko * 16 + (lane & 3) * 2;
            unsigned bh[4][2], bl[4][2];
            #pragma unroll
            for (int j = 0; j < 4; j++) {
                const int bn = wn * 32 + j * 8 + (lane >> 2);
                bh[j][0] = *(unsigned*)&sm.Bh[bn][kc];
                bh[j][1] = *(unsigned*)&sm.Bh[bn][kc + 8];
                bl[j][0] = *(unsigned*)&sm.Bl[bn][kc];
                bl[j][1] = *(unsigned*)&sm.Bl[bn][kc + 8];
            }
            #pragma unroll
            for (int i = 0; i < 4; i++) {
                const int ar = wm * 64 + i * 16 + (lane >> 2);
                unsigned ah[4], al[4];
                ah[0] = *(unsigned*)&sm.Ah[ar][kc];
                ah[1] = *(unsigned*)&sm.Ah[ar + 8][kc];
                ah[2] = *(unsigned*)&sm.Ah[ar][kc + 8];
                ah[3] = *(unsigned*)&sm.Ah[ar + 8][kc + 8];
                al[0] = *(unsigned*)&sm.Al[ar][kc];
                al[1] = *(unsigned*)&sm.Al[ar + 8][kc];
                al[2] = *(unsigned*)&sm.Al[ar][kc + 8];
                al[3] = *(unsigned*)&sm.Al[ar + 8][kc + 8];
                #pragma unroll
                for (int j = 0; j < 4; j++) {
                    mma16816(acc[i][j], ah, bh[j]);
                    mma16816(acc[i][j], ah, bl[j]);
                    mma16816(acc[i][j], al, bh[j]);
                }
            }
        }
        __syncthreads();
    }

    #pragma unroll
    for (int i = 0; i < 4; i++) {
        const int row = m0 + wm * 64 + i * 16 + (lane >> 2);
        #pragma unroll
        for (int j = 0; j < 4; j++) {
            const int col = wn * 32 + j * 8 + (lane & 3) * 2;
            const float2 bb = *(const float2*)&biasblk[col];
            float2 o0, o1;
            o0.x = acc[i][j][0] + bb.x; o0.y = acc[i][j][1] + bb.y;
            o1.x = acc[i][j][2] + bb.x; o1.y = acc[i][j][3] + bb.y;
            *(float2*)&Cblk[(size_t)row * ldc + col] = o0;
            *(float2*)&Cblk[(size_t)(row + 8) * ldc + col] = o1;
        }
    }
}

__global__ void __launch_bounds__(256, 1) qkv_gemm_kernel(
    const float* __restrict__ x,
    const float* __restrict__ wq, const float* __restrict__ bq,
    const float* __restrict__ wk, const float* __restrict__ bk,
    const float* __restrict__ wv, const float* __restrict__ bv)
{
    __shared__ MmaSmem sm;
    const int nb = blockIdx.x;
    const int m0 = blockIdx.y * 128;
    if (nb < 16) {
        const int off = nb * 128;
        mma_tile_128(x, wq + (size_t)off * DIM, bq + off, g_q + off,
                     QSTRIDE, m0, DIM, sm);
    } else if (nb < 20) {
        const int off = (nb - 16) * 128;
        mma_tile_128(x, wk + (size_t)off * DIM, bk + off, g_k + off,
                     KSTRIDE, m0, DIM, sm);
    } else {
        const int off = (nb - 20) * 128;
        mma_tile_128(x, wv + (size_t)off * DIM, bv + off, g_v + off,
                     KSTRIDE, m0, DIM, sm);
    }
}

__global__ void __launch_bounds__(256, 1) out_gemm_kernel(
    const float* __restrict__ wo, const float* __restrict__ bo,
    float* __restrict__ out)
{
    __shared__ MmaSmem sm;
    const int off = blockIdx.x * 128;
    mma_tile_128(g_ao, wo + (size_t)off * DIM, bo + off, out + off,
                 DIM, blockIdx.y * 128, DIM, sm);
}

// ---------------------------------------------------------------------------
// RoPE (in place)
// ---------------------------------------------------------------------------
__global__ void rope_kernel(const float* __restrict__ rope, int is_q)
{
    float* buf = is_q ? g_q : g_k;
    const int nh = is_q ? NH : NKVH;
    const int total = SEQ * nh * 32;
    int idx = blockIdx.x * blockDim.x + threadIdx.x;
    if (idx >= total) return;
    const int d = idx & 31;
    const int h = (idx >> 5) % nh;
    const int s = idx / (32 * nh);
    const float c  = rope[s * 128 + d];
    const float sn = rope[s * 128 + 64 + d];
    float* row = buf + (size_t)s * (nh * HD) + h * HD;
    const float x0 = row[d];
    const float x1 = row[d + 32];
    row[d]      = x0 * c - x1 * sn;
    row[d + 32] = x1 * c + x0 * sn;
}

// ---------------------------------------------------------------------------
// Tensor-core flash attention (split-3 on BOTH S=QK^T and O=PV).
// Block: 128 threads / 4 warps, q-tile 128 rows (warp = 32 rows = 2 m16 tiles).
// KV tiles of 64. V stored transposed hi+lo: O += ph*vh + ph*vl + pl*vh.
// ---------------------------------------------------------------------------
#define FP 68   // smem pitch in bf16

struct FlashSmem {
    __nv_bfloat16 Qh[128][FP];
    __nv_bfloat16 Ql[128][FP];
    __nv_bfloat16 Khi[64][FP];
    __nv_bfloat16 Klo[64][FP];
    __nv_bfloat16 Vthi[64][FP];    // Vt[hd][key] hi
    __nv_bfloat16 Vtlo[64][FP];    // Vt[hd][key] lo
};

__global__ void __launch_bounds__(128, 2) flash_mma_kernel(
    const float* __restrict__ sinks)
{
    extern __shared__ char smem_raw[];
    FlashSmem& sm = *(FlashSmem*)smem_raw;

    const int h    = blockIdx.y;
    const int kvh  = h >> 2;                 // REP = 4
    const int qt   = 15 - blockIdx.x;        // heavy blocks first
    const int q0   = qt * 128;
    const int tid  = threadIdx.x;
    const int lane = tid & 31;
    const int w    = tid >> 5;
    const int g    = lane >> 2;              // 0..7
    const int qd   = (lane & 3) * 2;         // 0,2,4,6

    // ---- stage Q (scaled, split hi/lo) into smem ----
    #pragma unroll
    for (int i = 0; i < 16; i++) {
        const int lin = tid + i * 128;       // 0..2047 float4 tasks
        const int r = lin >> 4, c4 = (lin & 15) * 4;
        float4 qv = *(const float4*)&g_q[(size_t)(q0 + r) * QSTRIDE + h * HD + c4];
        qv.x *= 0.125f; qv.y *= 0.125f; qv.z *= 0.125f; qv.w *= 0.125f;
        unsigned h01, h23, l01, l23;
        split4(qv, h01, h23, l01, l23);
        *(uint2*)&sm.Qh[r][c4] = make_uint2(h01, h23);
        *(uint2*)&sm.Ql[r][c4] = make_uint2(l01, l23);
    }

    // running state
    float o[2][8][4];
    #pragma unroll
    for (int mt = 0; mt < 2; mt++)
        #pragma unroll
        for (int j = 0; j < 8; j++)
            #pragma unroll
            for (int c = 0; c < 4; c++) o[mt][j][c] = 0.f;
    float mrow[2][2] = {{-1e30f, -1e30f}, {-1e30f, -1e30f}};
    float lrow[2][2] = {{0.f, 0.f}, {0.f, 0.f}};

    const int nfull  = 2 * qt;
    const int ntiles = 2 * qt + 2;

    for (int t = 0; t < ntiles; t++) {
        const int kbase = t * 64;
        // ---- load K tile (split hi/lo, row-major) ----
        #pragma unroll
        for (int i = 0; i < 8; i++) {
            const int lin = tid + i * 128;   // 1024 float4 tasks
            const int r = lin >> 4, c4 = (lin & 15) * 4;
            float4 kv = *(const float4*)&g_k[(size_t)(kbase + r) * KSTRIDE + kvh * HD + c4];
            unsigned h01, h23, l01, l23;
            split4(kv, h01, h23, l01, l23);
            *(uint2*)&sm.Khi[r][c4] = make_uint2(h01, h23);
            *(uint2*)&sm.Klo[r][c4] = make_uint2(l01, l23);
        }
        // ---- load V transposed (hi + lo): Vt[hd][key] ----
        #pragma unroll
        for (int i = 0; i < 8; i++) {
            const int lin = tid + i * 128;   // 1024 tasks: (hd c, key group r0)
            const int c = lin & 63, r0 = (lin >> 6) * 4;
            const size_t vb = (size_t)(kbase + r0) * KSTRIDE + kvh * HD + c;
            float v0 = g_v[vb];
            float v1 = g_v[vb + KSTRIDE];
            float v2 = g_v[vb + 2 * KSTRIDE];
            float v3 = g_v[vb + 3 * KSTRIDE];
            unsigned h01, l01, h23, l23;
            packbf_hl(v0, v1, h01, l01);
            packbf_hl(v2, v3, h23, l23);
            *(uint2*)&sm.Vthi[c][r0] = make_uint2(h01, h23);
            *(uint2*)&sm.Vtlo[c][r0] = make_uint2(l01, l23);
        }
        __syncthreads();

        // ---- S = Q K^T (split-3) ----
        float s[2][8][4];
        #pragma unroll
        for (int mt = 0; mt < 2; mt++)
            #pragma unroll
            for (int j = 0; j < 8; j++)
                #pragma unroll
                for (int c = 0; c < 4; c++) s[mt][j][c] = 0.f;

        #pragma unroll
        for (int kt = 0; kt < 4; kt++) {
            const int kc = kt * 16 + qd;
            unsigned ah[2][4], al[2][4];
            #pragma unroll
            for (int mt = 0; mt < 2; mt++) {
                const int ar = w * 32 + mt * 16 + g;
                ah[mt][0] = *(unsigned*)&sm.Qh[ar][kc];
                ah[mt][1] = *(unsigned*)&sm.Qh[ar + 8][kc];
                ah[mt][2] = *(unsigned*)&sm.Qh[ar][kc + 8];
                ah[mt][3] = *(unsigned*)&sm.Qh[ar + 8][kc + 8];
                al[mt][0] = *(unsigned*)&sm.Ql[ar][kc];
                al[mt][1] = *(unsigned*)&sm.Ql[ar + 8][kc];
                al[mt][2] = *(unsigned*)&sm.Ql[ar][kc + 8];
                al[mt][3] = *(unsigned*)&sm.Ql[ar + 8][kc + 8];
            }
            #pragma unroll
            for (int jk = 0; jk < 8; jk++) {
                const int bn = jk * 8 + g;
                unsigned bh[2], bl[2];
                bh[0] = *(unsigned*)&sm.Khi[bn][kc];
                bh[1] = *(unsigned*)&sm.Khi[bn][kc + 8];
                bl[0] = *(unsigned*)&sm.Klo[bn][kc];
                bl[1] = *(unsigned*)&sm.Klo[bn][kc + 8];
                #pragma unroll
                for (int mt = 0; mt < 2; mt++) {
                    mma16816(s[mt][jk], ah[mt], bh);
                    mma16816(s[mt][jk], ah[mt], bl);
                    mma16816(s[mt][jk], al[mt], bh);
                }
            }
        }

        // ---- causal mask (diagonal tiles only) ----
        if (t >= nfull) {
            #pragma unroll
            for (int mt = 0; mt < 2; mt++) {
                #pragma unroll
                for (int half = 0; half < 2; half++) {
                    const int qr = q0 + w * 32 + mt * 16 + g + half * 8;
                    #pragma unroll
                    for (int jk = 0; jk < 8; jk++) {
                        const int k0 = kbase + jk * 8 + qd;
                        if (k0 > qr)     s[mt][jk][half * 2]     = -1e30f;
                        if (k0 + 1 > qr) s[mt][jk][half * 2 + 1] = -1e30f;
                    }
                }
            }
        }

        // ---- online softmax ----
        unsigned pah[2][4][4], pal[2][4][4];
        #pragma unroll
        for (int mt = 0; mt < 2; mt++) {
            #pragma unroll
            for (int half = 0; half < 2; half++) {
                float mx = -1e30f;
                #pragma unroll
                for (int jk = 0; jk < 8; jk++) {
                    mx = fmaxf(mx, fmaxf(s[mt][jk][half * 2], s[mt][jk][half * 2 + 1]));
                }
                mx = fmaxf(mx, __shfl_xor_sync(0xffffffffu, mx, 1));
                mx = fmaxf(mx, __shfl_xor_sync(0xffffffffu, mx, 2));
                const float mold = mrow[mt][half];
                const float mnew = fmaxf(mold, mx);
                const float corr = __expf(mold - mnew);
                mrow[mt][half] = mnew;
                float ps = 0.f;
                #pragma unroll
                for (int jk = 0; jk < 8; jk++) {
                    float p0 = __expf(s[mt][jk][half * 2]     - mnew);
                    float p1 = __expf(s[mt][jk][half * 2 + 1] - mnew);
                    s[mt][jk][half * 2]     = p0;
                    s[mt][jk][half * 2 + 1] = p1;
                    ps += p0 + p1;
                }
                ps += __shfl_xor_sync(0xffffffffu, ps, 1);
                ps += __shfl_xor_sync(0xffffffffu, ps, 2);
                lrow[mt][half] = lrow[mt][half] * corr + ps;
                #pragma unroll
                for (int jn = 0; jn < 8; jn++) {
                    o[mt][jn][half * 2]     *= corr;
                    o[mt][jn][half * 2 + 1] *= corr;
                }
            }
            // pack P (exact hi/lo split) into A-fragments (FA2 layout identity)
            #pragma unroll
            for (int kt = 0; kt < 4; kt++) {
                packbf_hl(s[mt][2 * kt][0],     s[mt][2 * kt][1],
                          pah[mt][kt][0], pal[mt][kt][0]);
                packbf_hl(s[mt][2 * kt][2],     s[mt][2 * kt][3],
                          pah[mt][kt][1], pal[mt][kt][1]);
                packbf_hl(s[mt][2 * kt + 1][0], s[mt][2 * kt + 1][1],
                          pah[mt][kt][2], pal[mt][kt][2]);
                packbf_hl(s[mt][2 * kt + 1][2], s[mt][2 * kt + 1][3],
                          pah[mt][kt][3], pal[mt][kt][3]);
            }
        }

        // ---- O += P V (split-3) ----
        #pragma unroll
        for (int kt = 0; kt < 4; kt++) {
            const int kc = kt * 16 + qd;
            #pragma unroll
            for (int jn = 0; jn < 8; jn++) {
                const int bn = jn * 8 + g;
                unsigned vh[2], vl[2];
                vh[0] = *(unsigned*)&sm.Vthi[bn][kc];
                vh[1] = *(unsigned*)&sm.Vthi[bn][kc + 8];
                vl[0] = *(unsigned*)&sm.Vtlo[bn][kc];
                vl[1] = *(unsigned*)&sm.Vtlo[bn][kc + 8];
                #pragma unroll
                for (int mt = 0; mt < 2; mt++) {
                    mma16816(o[mt][jn], pah[mt][kt], vh);
                    mma16816(o[mt][jn], pah[mt][kt], vl);
                    mma16816(o[mt][jn], pal[mt][kt], vh);
                }
            }
        }
        __syncthreads();
    }

    // ---- sink renorm + store ----
    const float sk = sinks[h];
    float inv[2][2];
    #pragma unroll
    for (int mt = 0; mt < 2; mt++)
        #pragma unroll
        for (int half = 0; half < 2; half++) {
            const float lse = mrow[mt][half] + __logf(lrow[mt][half]);
            const float dmax = fmaxf(lse, sk);
            const float combined = dmax + log1pf(__expf(-fabsf(lse - sk)));
            const float r = __expf(fmaxf(lse - combined, -20.f));
            inv[mt][half] = r / lrow[mt][half];
        }

    #pragma unroll
    for (int mt = 0; mt < 2; mt++) {
        #pragma unroll
        for (int half = 0; half < 2; half++) {
            const int row = q0 + w * 32 + mt * 16 + g + half * 8;
            float* orow = g_ao + (size_t)row * QSTRIDE + h * HD;
            #pragma unroll
            for (int jn = 0; jn < 8; jn++) {
                float2 ov;
                ov.x = o[mt][jn][half * 2]     * inv[mt][half];
                ov.y = o[mt][jn][half * 2 + 1] * inv[mt][half];
                *(float2*)&orow[jn * 8 + qd] = ov;
            }
        }
    }
}

// ---------------------------------------------------------------------------
extern "C" void kernel_launch(void* const* d_in, const int* in_sizes, int n_in,
                              void* d_out, int out_size)
{
    const float* x     = (const float*)d_in[0];
    const float* rope  = (const float*)d_in[1];
    const float* wq    = (const float*)d_in[2];
    const float* bq    = (const float*)d_in[3];
    const float* wk    = (const float*)d_in[4];
    const float* bk    = (const float*)d_in[5];
    const float* wv    = (const float*)d_in[6];
    const float* bv    = (const float*)d_in[7];
    const float* wo    = (const float*)d_in[8];
    const float* bo    = (const float*)d_in[9];
    const float* sinks = (const float*)d_in[10];
    float* out = (float*)d_out;

    // 1) fused QKV projection (tensor core, bf16 split-3)
    qkv_gemm_kernel<<<dim3(24, 16), 256>>>(x, wq, bq, wk, bk, wv, bv);

    // 2) RoPE on q and k
    {
        const int tq = SEQ * NH * 32;
        rope_kernel<<<(tq + 255) / 256, 256>>>(rope, 1);
        const int tk = SEQ * NKVH * 32;
        rope_kernel<<<(tk + 255) / 256, 256>>>(rope, 0);
    }

    // 3) causal flash attention + sink renorm (tensor core, split-3 PV)
    cudaFuncSetAttribute(flash_mma_kernel,
                         cudaFuncAttributeMaxDynamicSharedMemorySize,
                         (int)sizeof(FlashSmem));
    flash_mma_kernel<<<dim3(16, NH), 128, sizeof(FlashSmem)>>>(sinks);

    // 4) output projection (tensor core, bf16 split-3)
    out_gemm_kernel<<<dim3(16, 16), 256>>>(wo, bo, out);
}

// round 16
// speedup vs baseline: 3.0531x; 1.0032x over previous
#include <cuda_runtime.h>
#include <cuda_bf16.h>
#include <math.h>

#define SEQ 2048
#define DIM 2048
#define NH 32
#define NKVH 8
#define HD 64
#define QSTRIDE (NH*HD)     // 2048
#define KSTRIDE (NKVH*HD)   // 512

typedef unsigned long long ull;

// fp32 scratch
__device__ float g_q[SEQ * QSTRIDE];
__device__ float g_k[SEQ * KSTRIDE];
__device__ float g_v[SEQ * KSTRIDE];
__device__ float g_ao[SEQ * QSTRIDE];

// pre-split hi/lo bf16 operands, interleaved {h01,h23,l01,l23} per 4 elements.
// word i corresponds 1:1 with float element i of the source array.
__device__ unsigned g_xhl [SEQ * DIM];
__device__ unsigned g_wqhl[QSTRIDE * DIM];
__device__ unsigned g_wkhl[KSTRIDE * DIM];
__device__ unsigned g_wvhl[KSTRIDE * DIM];
__device__ unsigned g_wohl[DIM * QSTRIDE];
__device__ unsigned g_aohl[SEQ * QSTRIDE];
__device__ unsigned g_khl [SEQ * KSTRIDE];
__device__ unsigned g_vthl[NKVH * HD * SEQ];   // [kvh][hd][seq]

// ---------------------------------------------------------------------------
// mma + bf16 split helpers
// ---------------------------------------------------------------------------
__device__ __forceinline__ void mma16816(float* d, const unsigned* a, const unsigned* b) {
    asm volatile(
        "mma.sync.aligned.m16n8k16.row.col.f32.bf16.bf16.f32 "
        "{%0,%1,%2,%3}, {%4,%5,%6,%7}, {%8,%9}, {%0,%1,%2,%3};"
        : "+f"(d[0]), "+f"(d[1]), "+f"(d[2]), "+f"(d[3])
        : "r"(a[0]), "r"(a[1]), "r"(a[2]), "r"(a[3]), "r"(b[0]), "r"(b[1]));
}

__device__ __forceinline__ void split4(float4 v, unsigned& h01, unsigned& h23,
                                       unsigned& l01, unsigned& l23) {
    __nv_bfloat16 hx = __float2bfloat16_rn(v.x);
    __nv_bfloat16 hy = __float2bfloat16_rn(v.y);
    __nv_bfloat16 hz = __float2bfloat16_rn(v.z);
    __nv_bfloat16 hw = __float2bfloat16_rn(v.w);
    __nv_bfloat162 hp0 = __halves2bfloat162(hx, hy);
    __nv_bfloat162 hp1 = __halves2bfloat162(hz, hw);
    __nv_bfloat162 lp0 = __halves2bfloat162(
        __float2bfloat16_rn(v.x - __bfloat162float(hx)),
        __float2bfloat16_rn(v.y - __bfloat162float(hy)));
    __nv_bfloat162 lp1 = __halves2bfloat162(
        __float2bfloat16_rn(v.z - __bfloat162float(hz)),
        __float2bfloat16_rn(v.w - __bfloat162float(hw)));
    h01 = *(unsigned*)&hp0; h23 = *(unsigned*)&hp1;
    l01 = *(unsigned*)&lp0; l23 = *(unsigned*)&lp1;
}

__device__ __forceinline__ void packbf_hl(float a, float b,
                                          unsigned& hi, unsigned& lo) {
    __nv_bfloat16 ha = __float2bfloat16_rn(a);
    __nv_bfloat16 hb = __float2bfloat16_rn(b);
    __nv_bfloat162 hp = __halves2bfloat162(ha, hb);
    __nv_bfloat162 lp = __halves2bfloat162(
        __float2bfloat16_rn(a - __bfloat162float(ha)),
        __float2bfloat16_rn(b - __bfloat162float(hb)));
    hi = *(unsigned*)&hp;
    lo = *(unsigned*)&lp;
}

// ---------------------------------------------------------------------------
// Converters
// ---------------------------------------------------------------------------
__global__ void convert_hl_kernel(const float* __restrict__ src,
                                  unsigned* __restrict__ dst, int n4)
{
    const int g = blockIdx.x * blockDim.x + threadIdx.x;
    if (g >= n4) return;
    float4 v = ((const float4*)src)[g];
    unsigned h01, h23, l01, l23;
    split4(v, h01, h23, l01, l23);
    ((uint4*)dst)[g] = make_uint4(h01, h23, l01, l23);
}

// transpose V [seq][kvh*64+hd] -> g_vthl [kvh][hd][seq] (hl-interleaved)
// grid (SEQ/64, NKVH), 256 threads
__global__ void vt_convert_kernel()
{
    __shared__ float tile[64][65];
    const int kvh = blockIdx.y;
    const int s0  = blockIdx.x * 64;
    const int tid = threadIdx.x;
    #pragma unroll
    for (int i = 0; i < 4; i++) {
        const int lin = tid + i * 256;
        const int r = lin >> 4, c4 = (lin & 15) * 4;
        float4 v = *(const float4*)&g_v[(size_t)(s0 + r) * KSTRIDE + kvh * HD + c4];
        tile[r][c4 + 0] = v.x; tile[r][c4 + 1] = v.y;
        tile[r][c4 + 2] = v.z; tile[r][c4 + 3] = v.w;
    }
    __syncthreads();
    #pragma unroll
    for (int i = 0; i < 4; i++) {
        const int lin = tid + i * 256;
        const int hd = lin >> 4, sg4 = (lin & 15) * 4;
        unsigned h01, l01, h23, l23;
        packbf_hl(tile[sg4 + 0][hd], tile[sg4 + 1][hd], h01, l01);
        packbf_hl(tile[sg4 + 2][hd], tile[sg4 + 3][hd], h23, l23);
        const size_t e = (size_t)(kvh * HD + hd) * SEQ + s0 + sg4;
        *(uint4*)&g_vthl[e] = make_uint4(h01, h23, l01, l23);
    }
}

// ---------------------------------------------------------------------------
// Tensor-core GEMM (bf16 split-3), operands pre-split in global.
// Inner fragment/MMA structure identical to the validated R12 kernel.
// ---------------------------------------------------------------------------
struct MmaSmem {
    __nv_bfloat16 Ah[128][40];
    __nv_bfloat16 Al[128][40];
    __nv_bfloat16 Bh[128][40];
    __nv_bfloat16 Bl[128][40];
};

__device__ __forceinline__ void mma_tile_128(
    const unsigned* __restrict__ Xhl, const unsigned* __restrict__ Whl,
    const float* __restrict__ biasblk, float* __restrict__ Cblk,
    int ldc, int m0, int K, MmaSmem& sm)
{
    const int tid  = threadIdx.x;
    const int lane = tid & 31;
    const int wid  = tid >> 5;
    const int wm   = wid & 1;
    const int wn   = wid >> 1;

    float acc[4][4][4];
    #pragma unroll
    for (int i = 0; i < 4; i++)
        #pragma unroll
        for (int j = 0; j < 4; j++)
            #pragma unroll
            for (int c = 0; c < 4; c++) acc[i][j][c] = 0.f;

    uint4 apf[4], bpf[4];
    #pragma unroll
    for (int i = 0; i < 4; i++) {
        const int lin = tid + i * 256;
        const int r = lin >> 3, kc = (lin & 7) * 4;
        apf[i] = *(const uint4*)&Xhl[(size_t)(m0 + r) * K + kc];
        bpf[i] = *(const uint4*)&Whl[(size_t)r * K + kc];
    }

    const int nt = K >> 5;
    for (int kt = 0; kt < nt; kt++) {
        #pragma unroll
        for (int i = 0; i < 4; i++) {
            const int lin = tid + i * 256;
            const int r = lin >> 3, kc = (lin & 7) * 4;
            *(uint2*)&sm.Ah[r][kc] = make_uint2(apf[i].x, apf[i].y);
            *(uint2*)&sm.Al[r][kc] = make_uint2(apf[i].z, apf[i].w);
            *(uint2*)&sm.Bh[r][kc] = make_uint2(bpf[i].x, bpf[i].y);
            *(uint2*)&sm.Bl[r][kc] = make_uint2(bpf[i].z, bpf[i].w);
        }
        __syncthreads();

        if (kt + 1 < nt) {
            const int kb = (kt + 1) * 32;
            #pragma unroll
            for (int i = 0; i < 4; i++) {
                const int lin = tid + i * 256;
                const int r = lin >> 3, kc = (lin & 7) * 4;
                apf[i] = *(const uint4*)&Xhl[(size_t)(m0 + r) * K + kb + kc];
                bpf[i] = *(const uint4*)&Whl[(size_t)r * K + kb + kc];
            }
        }

        #pragma unroll
        for (int ko = 0; ko < 2; ko++) {
            const int kc = ko * 16 + (lane & 3) * 2;
            unsigned bh[4][2], bl[4][2];
            #pragma unroll
            for (int j = 0; j < 4; j++) {
                const int bn = wn * 32 + j * 8 + (lane >> 2);
                bh[j][0] = *(unsigned*)&sm.Bh[bn][kc];
                bh[j][1] = *(unsigned*)&sm.Bh[bn][kc + 8];
                bl[j][0] = *(unsigned*)&sm.Bl[bn][kc];
                bl[j][1] = *(unsigned*)&sm.Bl[bn][kc + 8];
            }
            #pragma unroll
            for (int i = 0; i < 4; i++) {
                const int ar = wm * 64 + i * 16 + (lane >> 2);
                unsigned ah[4], al[4];
                ah[0] = *(unsigned*)&sm.Ah[ar][kc];
                ah[1] = *(unsigned*)&sm.Ah[ar + 8][kc];
                ah[2] = *(unsigned*)&sm.Ah[ar][kc + 8];
                ah[3] = *(unsigned*)&sm.Ah[ar + 8][kc + 8];
                al[0] = *(unsigned*)&sm.Al[ar][kc];
                al[1] = *(unsigned*)&sm.Al[ar + 8][kc];
                al[2] = *(unsigned*)&sm.Al[ar][kc + 8];
                al[3] = *(unsigned*)&sm.Al[ar + 8][kc + 8];
                #pragma unroll
                for (int j = 0; j < 4; j++) {
                    mma16816(acc[i][j], ah, bh[j]);
                    mma16816(acc[i][j], ah, bl[j]);
                    mma16816(acc[i][j], al, bh[j]);
                }
            }
        }
        __syncthreads();
    }

    #pragma unroll
    for (int i = 0; i < 4; i++) {
        const int row = m0 + wm * 64 + i * 16 + (lane >> 2);
        #pragma unroll
        for (int j = 0; j < 4; j++) {
            const int col = wn * 32 + j * 8 + (lane & 3) * 2;
            const float2 bb = *(const float2*)&biasblk[col];
            float2 o0, o1;
            o0.x = acc[i][j][0] + bb.x; o0.y = acc[i][j][1] + bb.y;
            o1.x = acc[i][j][2] + bb.x; o1.y = acc[i][j][3] + bb.y;
            *(float2*)&Cblk[(size_t)row * ldc + col] = o0;
            *(float2*)&Cblk[(size_t)(row + 8) * ldc + col] = o1;
        }
    }
}

__global__ void __launch_bounds__(256, 1) qkv_gemm_kernel(
    const float* __restrict__ bq, const float* __restrict__ bk,
    const float* __restrict__ bv)
{
    __shared__ MmaSmem sm;
    const int nb = blockIdx.x;
    const int m0 = blockIdx.y * 128;
    if (nb < 16) {
        const int off = nb * 128;
        mma_tile_128(g_xhl, g_wqhl + (size_t)off * DIM, bq + off, g_q + off,
                     QSTRIDE, m0, DIM, sm);
    } else if (nb < 20) {
        const int off = (nb - 16) * 128;
        mma_tile_128(g_xhl, g_wkhl + (size_t)off * DIM, bk + off, g_k + off,
                     KSTRIDE, m0, DIM, sm);
    } else {
        const int off = (nb - 20) * 128;
        mma_tile_128(g_xhl, g_wvhl + (size_t)off * DIM, bv + off, g_v + off,
                     KSTRIDE, m0, DIM, sm);
    }
}

__global__ void __launch_bounds__(256, 1) out_gemm_kernel(
    const float* __restrict__ bo, float* __restrict__ out)
{
    __shared__ MmaSmem sm;
    const int off = blockIdx.x * 128;
    mma_tile_128(g_aohl, g_wohl + (size_t)off * DIM, bo + off, out + off,
                 DIM, blockIdx.y * 128, DIM, sm);
}

// ---------------------------------------------------------------------------
// RoPE (in place, fp32)
// ---------------------------------------------------------------------------
__global__ void rope_kernel(const float* __restrict__ rope, int is_q)
{
    float* buf = is_q ? g_q : g_k;
    const int nh = is_q ? NH : NKVH;
    const int total = SEQ * nh * 32;
    int idx = blockIdx.x * blockDim.x + threadIdx.x;
    if (idx >= total) return;
    const int d = idx & 31;
    const int h = (idx >> 5) % nh;
    const int s = idx / (32 * nh);
    const float c  = rope[s * 128 + d];
    const float sn = rope[s * 128 + 64 + d];
    float* row = buf + (size_t)s * (nh * HD) + h * HD;
    const float x0 = row[d];
    const float x1 = row[d + 32];
    row[d]      = x0 * c - x1 * sn;
    row[d + 32] = x1 * c + x0 * sn;
}

// ---------------------------------------------------------------------------
// Tensor-core flash attention (split-3 on S=QK^T and O=PV).
// K and V^T read pre-split from global; Q split inline (used exactly once).
// ---------------------------------------------------------------------------
#define FP 68   // smem pitch in bf16

struct FlashSmem {
    __nv_bfloat16 Qh[128][FP];
    __nv_bfloat16 Ql[128][FP];
    __nv_bfloat16 Khi[64][FP];
    __nv_bfloat16 Klo[64][FP];
    __nv_bfloat16 Vthi[64][FP];    // Vt[hd][key] hi
    __nv_bfloat16 Vtlo[64][FP];    // Vt[hd][key] lo
};

__global__ void __launch_bounds__(128, 2) flash_mma_kernel(
    const float* __restrict__ sinks)
{
    extern __shared__ char smem_raw[];
    FlashSmem& sm = *(FlashSmem*)smem_raw;

    const int h    = blockIdx.y;
    const int kvh  = h >> 2;                 // REP = 4
    const int qt   = 15 - blockIdx.x;        // heavy blocks first
    const int q0   = qt * 128;
    const int tid  = threadIdx.x;
    const int lane = tid & 31;
    const int w    = tid >> 5;
    const int g    = lane >> 2;              // 0..7
    const int qd   = (lane & 3) * 2;         // 0,2,4,6

    // ---- stage Q (scaled, split hi/lo) into smem ----
    #pragma unroll
    for (int i = 0; i < 16; i++) {
        const int lin = tid + i * 128;
        const int r = lin >> 4, c4 = (lin & 15) * 4;
        float4 qv = *(const float4*)&g_q[(size_t)(q0 + r) * QSTRIDE + h * HD + c4];
        qv.x *= 0.125f; qv.y *= 0.125f; qv.z *= 0.125f; qv.w *= 0.125f;
        unsigned h01, h23, l01, l23;
        split4(qv, h01, h23, l01, l23);
        *(uint2*)&sm.Qh[r][c4] = make_uint2(h01, h23);
        *(uint2*)&sm.Ql[r][c4] = make_uint2(l01, l23);
    }

    float o[2][8][4];
    #pragma unroll
    for (int mt = 0; mt < 2; mt++)
        #pragma unroll
        for (int j = 0; j < 8; j++)
            #pragma unroll
            for (int c = 0; c < 4; c++) o[mt][j][c] = 0.f;
    float mrow[2][2] = {{-1e30f, -1e30f}, {-1e30f, -1e30f}};
    float lrow[2][2] = {{0.f, 0.f}, {0.f, 0.f}};

    const int nfull  = 2 * qt;
    const int ntiles = 2 * qt + 2;

    for (int t = 0; t < ntiles; t++) {
        const int kbase = t * 64;
        // ---- K tile: pre-split hl load ----
        #pragma unroll
        for (int i = 0; i < 8; i++) {
            const int lin = tid + i * 128;
            const int r = lin >> 4, c4 = (lin & 15) * 4;
            uint4 kv = *(const uint4*)&g_khl[(size_t)(kbase + r) * KSTRIDE + kvh * HD + c4];
            *(uint2*)&sm.Khi[r][c4] = make_uint2(kv.x, kv.y);
            *(uint2*)&sm.Klo[r][c4] = make_uint2(kv.z, kv.w);
        }
        // ---- V^T tile: pre-split, pre-transposed ----
        #pragma unroll
        for (int i = 0; i < 8; i++) {
            const int lin = tid + i * 128;
            const int c = lin >> 4, r0 = (lin & 15) * 4;
            uint4 vv = *(const uint4*)&g_vthl[(size_t)(kvh * HD + c) * SEQ + kbase + r0];
            *(uint2*)&sm.Vthi[c][r0] = make_uint2(vv.x, vv.y);
            *(uint2*)&sm.Vtlo[c][r0] = make_uint2(vv.z, vv.w);
        }
        __syncthreads();

        // ---- S = Q K^T (split-3) ----
        float s[2][8][4];
        #pragma unroll
        for (int mt = 0; mt < 2; mt++)
            #pragma unroll
            for (int j = 0; j < 8; j++)
                #pragma unroll
                for (int c = 0; c < 4; c++) s[mt][j][c] = 0.f;

        #pragma unroll
        for (int kt = 0; kt < 4; kt++) {
            const int kc = kt * 16 + qd;
            unsigned ah[2][4], al[2][4];
            #pragma unroll
            for (int mt = 0; mt < 2; mt++) {
                const int ar = w * 32 + mt * 16 + g;
                ah[mt][0] = *(unsigned*)&sm.Qh[ar][kc];
                ah[mt][1] = *(unsigned*)&sm.Qh[ar + 8][kc];
                ah[mt][2] = *(unsigned*)&sm.Qh[ar][kc + 8];
                ah[mt][3] = *(unsigned*)&sm.Qh[ar + 8][kc + 8];
                al[mt][0] = *(unsigned*)&sm.Ql[ar][kc];
                al[mt][1] = *(unsigned*)&sm.Ql[ar + 8][kc];
                al[mt][2] = *(unsigned*)&sm.Ql[ar][kc + 8];
                al[mt][3] = *(unsigned*)&sm.Ql[ar + 8][kc + 8];
            }
            #pragma unroll
            for (int jk = 0; jk < 8; jk++) {
                const int bn = jk * 8 + g;
                unsigned bh[2], bl[2];
                bh[0] = *(unsigned*)&sm.Khi[bn][kc];
                bh[1] = *(unsigned*)&sm.Khi[bn][kc + 8];
                bl[0] = *(unsigned*)&sm.Klo[bn][kc];
                bl[1] = *(unsigned*)&sm.Klo[bn][kc + 8];
                #pragma unroll
                for (int mt = 0; mt < 2; mt++) {
                    mma16816(s[mt][jk], ah[mt], bh);
                    mma16816(s[mt][jk], ah[mt], bl);
                    mma16816(s[mt][jk], al[mt], bh);
                }
            }
        }

        // ---- causal mask (diagonal tiles only) ----
        if (t >= nfull) {
            #pragma unroll
            for (int mt = 0; mt < 2; mt++) {
                #pragma unroll
                for (int half = 0; half < 2; half++) {
                    const int qr = q0 + w * 32 + mt * 16 + g + half * 8;
                    #pragma unroll
                    for (int jk = 0; jk < 8; jk++) {
                        const int k0 = kbase + jk * 8 + qd;
                        if (k0 > qr)     s[mt][jk][half * 2]     = -1e30f;
                        if (k0 + 1 > qr) s[mt][jk][half * 2 + 1] = -1e30f;
                    }
                }
            }
        }

        // ---- online softmax ----
        unsigned pah[2][4][4], pal[2][4][4];
        #pragma unroll
        for (int mt = 0; mt < 2; mt++) {
            #pragma unroll
            for (int half = 0; half < 2; half++) {
                float mx = -1e30f;
                #pragma unroll
                for (int jk = 0; jk < 8; jk++) {
                    mx = fmaxf(mx, fmaxf(s[mt][jk][half * 2], s[mt][jk][half * 2 + 1]));
                }
                mx = fmaxf(mx, __shfl_xor_sync(0xffffffffu, mx, 1));
                mx = fmaxf(mx, __shfl_xor_sync(0xffffffffu, mx, 2));
                const float mold = mrow[mt][half];
                const float mnew = fmaxf(mold, mx);
                const float corr = __expf(mold - mnew);
                mrow[mt][half] = mnew;
                float ps = 0.f;
                #pragma unroll
                for (int jk = 0; jk < 8; jk++) {
                    float p0 = __expf(s[mt][jk][half * 2]     - mnew);
                    float p1 = __expf(s[mt][jk][half * 2 + 1] - mnew);
                    s[mt][jk][half * 2]     = p0;
                    s[mt][jk][half * 2 + 1] = p1;
                    ps += p0 + p1;
                }
                ps += __shfl_xor_sync(0xffffffffu, ps, 1);
                ps += __shfl_xor_sync(0xffffffffu, ps, 2);
                lrow[mt][half] = lrow[mt][half] * corr + ps;
                #pragma unroll
                for (int jn = 0; jn < 8; jn++) {
                    o[mt][jn][half * 2]     *= corr;
                    o[mt][jn][half * 2 + 1] *= corr;
                }
            }
            #pragma unroll
            for (int kt = 0; kt < 4; kt++) {
                packbf_hl(s[mt][2 * kt][0],     s[mt][2 * kt][1],
                          pah[mt][kt][0], pal[mt][kt][0]);
                packbf_hl(s[mt][2 * kt][2],     s[mt][2 * kt][3],
                          pah[mt][kt][1], pal[mt][kt][1]);
                packbf_hl(s[mt][2 * kt + 1][0], s[mt][2 * kt + 1][1],
                          pah[mt][kt][2], pal[mt][kt][2]);
                packbf_hl(s[mt][2 * kt + 1][2], s[mt][2 * kt + 1][3],
                          pah[mt][kt][3], pal[mt][kt][3]);
            }
        }

        // ---- O += P V (split-3) ----
        #pragma unroll
        for (int kt = 0; kt < 4; kt++) {
            const int kc = kt * 16 + qd;
            #pragma unroll
            for (int jn = 0; jn < 8; jn++) {
                const int bn = jn * 8 + g;
                unsigned vh[2], vl[2];
                vh[0] = *(unsigned*)&sm.Vthi[bn][kc];
                vh[1] = *(unsigned*)&sm.Vthi[bn][kc + 8];
                vl[0] = *(unsigned*)&sm.Vtlo[bn][kc];
                vl[1] = *(unsigned*)&sm.Vtlo[bn][kc + 8];
                #pragma unroll
                for (int mt = 0; mt < 2; mt++) {
                    mma16816(o[mt][jn], pah[mt][kt], vh);
                    mma16816(o[mt][jn], pah[mt][kt], vl);
                    mma16816(o[mt][jn], pal[mt][kt], vh);
                }
            }
        }
        __syncthreads();
    }

    // ---- sink renorm + store ----
    const float sk = sinks[h];
    float inv[2][2];
    #pragma unroll
    for (int mt = 0; mt < 2; mt++)
        #pragma unroll
        for (int half = 0; half < 2; half++) {
            const float lse = mrow[mt][half] + __logf(lrow[mt][half]);
            const float dmax = fmaxf(lse, sk);
            const float combined = dmax + log1pf(__expf(-fabsf(lse - sk)));
            const float r = __expf(fmaxf(lse - combined, -20.f));
            inv[mt][half] = r / lrow[mt][half];
        }

    #pragma unroll
    for (int mt = 0; mt < 2; mt++) {
        #pragma unroll
        for (int half = 0; half < 2; half++) {
            const int row = q0 + w * 32 + mt * 16 + g + half * 8;
            float* orow = g_ao + (size_t)row * QSTRIDE + h * HD;
            #pragma unroll
            for (int jn = 0; jn < 8; jn++) {
                float2 ov;
                ov.x = o[mt][jn][half * 2]     * inv[mt][half];
                ov.y = o[mt][jn][half * 2 + 1] * inv[mt][half];
                *(float2*)&orow[jn * 8 + qd] = ov;
            }
        }
    }
}

// ---------------------------------------------------------------------------
extern "C" void kernel_launch(void* const* d_in, const int* in_sizes, int n_in,
                              void* d_out, int out_size)
{
    const float* x     = (const float*)d_in[0];
    const float* rope  = (const float*)d_in[1];
    const float* wq    = (const float*)d_in[2];
    const float* bq    = (const float*)d_in[3];
    const float* wk    = (const float*)d_in[4];
    const float* bk    = (const float*)d_in[5];
    const float* wv    = (const float*)d_in[6];
    const float* bv    = (const float*)d_in[7];
    const float* wo    = (const float*)d_in[8];
    const float* bo    = (const float*)d_in[9];
    const float* sinks = (const float*)d_in[10];
    float* out = (float*)d_out;

    unsigned* p_xhl;  cudaGetSymbolAddress((void**)&p_xhl,  g_xhl);
    unsigned* p_wqhl; cudaGetSymbolAddress((void**)&p_wqhl, g_wqhl);
    unsigned* p_wkhl; cudaGetSymbolAddress((void**)&p_wkhl, g_wkhl);
    unsigned* p_wvhl; cudaGetSymbolAddress((void**)&p_wvhl, g_wvhl);
    unsigned* p_wohl; cudaGetSymbolAddress((void**)&p_wohl, g_wohl);
    unsigned* p_aohl; cudaGetSymbolAddress((void**)&p_aohl, g_aohl);
    unsigned* p_khl;  cudaGetSymbolAddress((void**)&p_khl,  g_khl);
    float*    p_k;    cudaGetSymbolAddress((void**)&p_k,    g_k);
    float*    p_ao;   cudaGetSymbolAddress((void**)&p_ao,   g_ao);

    // 0) pre-split x + weights to hi/lo bf16
    convert_hl_kernel<<<(SEQ*DIM/4 + 255)/256, 256>>>(x,  p_xhl,  SEQ*DIM/4);
    convert_hl_kernel<<<(QSTRIDE*DIM/4 + 255)/256, 256>>>(wq, p_wqhl, QSTRIDE*DIM/4);
    convert_hl_kernel<<<(KSTRIDE*DIM/4 + 255)/256, 256>>>(wk, p_wkhl, KSTRIDE*DIM/4);
    convert_hl_kernel<<<(KSTRIDE*DIM/4 + 255)/256, 256>>>(wv, p_wvhl, KSTRIDE*DIM/4);
    convert_hl_kernel<<<(DIM*QSTRIDE/4 + 255)/256, 256>>>(wo, p_wohl, DIM*QSTRIDE/4);

    // 1) fused QKV projection (tensor core, split-3, pre-split operands)
    qkv_gemm_kernel<<<dim3(24, 16), 256>>>(bq, bk, bv);

    // 2) RoPE on q and k (fp32)
    rope_kernel<<<(SEQ*NH*32 + 255)/256, 256>>>(rope, 1);
    rope_kernel<<<(SEQ*NKVH*32 + 255)/256, 256>>>(rope, 0);

    // 2b) pre-split K (post-rope) and transposed V
    convert_hl_kernel<<<(SEQ*KSTRIDE/4 + 255)/256, 256>>>(p_k, p_khl, SEQ*KSTRIDE/4);
    vt_convert_kernel<<<dim3(SEQ/64, NKVH), 256>>>();

    // 3) causal flash attention + sink renorm (tensor core)
    cudaFuncSetAttribute(flash_mma_kernel,
                         cudaFuncAttributeMaxDynamicSharedMemorySize,
                         (int)sizeof(FlashSmem));
    flash_mma_kernel<<<dim3(16, NH), 128, sizeof(FlashSmem)>>>(sinks);

    // 3b) pre-split attention output
    convert_hl_kernel<<<(SEQ*QSTRIDE/4 + 255)/256, 256>>>(p_ao, p_aohl, SEQ*QSTRIDE/4);

    // 4) output projection
    out_gemm_kernel<<<dim3(16, 16), 256>>>(bo, out);
}